// round 2
// baseline (speedup 1.0000x reference)
#include <cuda_runtime.h>

#define N_NODES 50000
#define HID 128
#define EF 64

// Scratch (device globals — allocation-free per harness rules)
__device__ float g_P   [(size_t)N_NODES * HID];   // node_feat @ W1_top + b1
__device__ float g_P3  [(size_t)N_NODES * HID];   // node_feat @ W3_top + b3
__device__ float g_sums[(size_t)N_NODES * HID];   // scatter-add target
__device__ float g_cnt [N_NODES];

// ---------------------------------------------------------------------------
__global__ void zero_kernel() {
    const size_t total4 = (size_t)N_NODES * HID / 4;
    float4* s = (float4*)g_sums;
    const float4 z = make_float4(0.f, 0.f, 0.f, 0.f);
    for (size_t i = (size_t)blockIdx.x * blockDim.x + threadIdx.x; i < total4;
         i += (size_t)gridDim.x * blockDim.x)
        s[i] = z;
    for (int i = blockIdx.x * blockDim.x + threadIdx.x; i < N_NODES;
         i += gridDim.x * blockDim.x)
        g_cnt[i] = 0.f;
}

// ---------------------------------------------------------------------------
// C[m][0:128] = A[m][0:128] @ W[128][128] + b   for m in [0, N_NODES)
// which==0 -> C = g_P, which==1 -> C = g_P3
__global__ __launch_bounds__(256, 1)
void pre_kernel(const float* __restrict__ A, const float* __restrict__ W,
                const float* __restrict__ b, int which) {
    extern __shared__ float sm[];
    float* sW = sm;              // 128*128
    float* sA = sm + 128 * 128;  // 128*128
    float* C = which ? g_P3 : g_P;

    const int tid = threadIdx.x;
    const int m0 = blockIdx.x * 128;

    {   // stage W
        const float4* src = (const float4*)W;
        float4* dst = (float4*)sW;
        #pragma unroll
        for (int i = 0; i < 16; i++) dst[tid + 256 * i] = src[tid + 256 * i];
    }
    // stage A tile (row-major)
    for (int i = tid; i < 4096; i += 256) {
        int m = i >> 5;
        int k4 = (i & 31) << 2;
        int gm = m0 + m;
        float4 v = make_float4(0.f, 0.f, 0.f, 0.f);
        if (gm < N_NODES) v = *(const float4*)(A + (size_t)gm * 128 + k4);
        *(float4*)(sA + m * 128 + k4) = v;
    }
    __syncthreads();

    const int tm = tid >> 4, tj = tid & 15;
    const int mb = tm * 8, jb = tj * 8;
    float acc[8][8];
    {
        float4 b0 = *(const float4*)(b + jb);
        float4 b1v = *(const float4*)(b + jb + 4);
        #pragma unroll
        for (int u = 0; u < 8; u++) {
            acc[u][0] = b0.x;  acc[u][1] = b0.y;  acc[u][2] = b0.z;  acc[u][3] = b0.w;
            acc[u][4] = b1v.x; acc[u][5] = b1v.y; acc[u][6] = b1v.z; acc[u][7] = b1v.w;
        }
    }
    #pragma unroll 4
    for (int k = 0; k < 128; k++) {
        float av[8], wv[8];
        #pragma unroll
        for (int u = 0; u < 8; u++) av[u] = sA[(mb + u) * 128 + k];
        float4 w0 = *(const float4*)(sW + k * 128 + jb);
        float4 w1 = *(const float4*)(sW + k * 128 + jb + 4);
        wv[0] = w0.x; wv[1] = w0.y; wv[2] = w0.z; wv[3] = w0.w;
        wv[4] = w1.x; wv[5] = w1.y; wv[6] = w1.z; wv[7] = w1.w;
        #pragma unroll
        for (int u = 0; u < 8; u++)
            #pragma unroll
            for (int v = 0; v < 8; v++) acc[u][v] += av[u] * wv[v];
    }
    #pragma unroll
    for (int u = 0; u < 8; u++) {
        int gm = m0 + mb + u;
        if (gm < N_NODES) {
            *(float4*)(C + (size_t)gm * 128 + jb) =
                make_float4(acc[u][0], acc[u][1], acc[u][2], acc[u][3]);
            *(float4*)(C + (size_t)gm * 128 + jb + 4) =
                make_float4(acc[u][4], acc[u][5], acc[u][6], acc[u][7]);
        }
    }
}

// ---------------------------------------------------------------------------
// Per 128-edge tile: h = relu(P[col] + edge_attr @ W1_bot); msg = h @ W2 + b2;
// atomicAdd msg into g_sums[row], count into g_cnt[row].
// edge_index is int32 (JAX default x64-disabled downcasts int64 -> int32).
__global__ __launch_bounds__(256, 1)
void edge_kernel(const float* __restrict__ ea, const int* __restrict__ eidx,
                 const float* __restrict__ W1, const float* __restrict__ W2,
                 const float* __restrict__ b2, int E) {
    extern __shared__ float sm[];
    float* sW1b = sm;                        // 64*128  = 8192
    float* sW2  = sm + 8192;                 // 128*128 = 16384
    float* sEA  = sm + 8192 + 16384;         // 128*64  = 8192
    float* sH   = sm + 8192 + 16384 + 8192;  // 128*128 = 16384
    int* s_row = (int*)(sm + 49152);
    int* s_col = s_row + 128;

    const int tid = threadIdx.x;
    const int e0 = blockIdx.x * 128;

    {   // W1 bottom (rows 128..191 multiply edge_attr)
        const float4* src = (const float4*)(W1 + 128 * 128);
        float4* dst = (float4*)sW1b;
        #pragma unroll
        for (int i = 0; i < 8; i++) dst[tid + 256 * i] = src[tid + 256 * i];
    }
    {
        const float4* src = (const float4*)W2;
        float4* dst = (float4*)sW2;
        #pragma unroll
        for (int i = 0; i < 16; i++) dst[tid + 256 * i] = src[tid + 256 * i];
    }
    for (int i = tid; i < 2048; i += 256) {
        int e = i >> 4;
        int k4 = (i & 15) << 2;
        float4 v = make_float4(0.f, 0.f, 0.f, 0.f);
        if (e0 + e < E) v = *(const float4*)(ea + (size_t)(e0 + e) * EF + k4);
        *(float4*)(sEA + e * EF + k4) = v;
    }
    if (tid < 128) {
        int e = e0 + tid;
        int r = 0, c = 0;
        if (e < E) { r = eidx[e]; c = eidx[(size_t)E + e]; }
        s_row[tid] = r;
        s_col[tid] = c;
    }
    __syncthreads();

    const int te = tid >> 4, tj = tid & 15;
    const int eb = te * 8, jb = tj * 8;
    float acc[8][8];

    // init: gather P[col] (b1 folded in)
    #pragma unroll
    for (int u = 0; u < 8; u++) {
        const float* p = g_P + (size_t)s_col[eb + u] * 128 + jb;
        float4 p0 = *(const float4*)p;
        float4 p1 = *(const float4*)(p + 4);
        acc[u][0] = p0.x; acc[u][1] = p0.y; acc[u][2] = p0.z; acc[u][3] = p0.w;
        acc[u][4] = p1.x; acc[u][5] = p1.y; acc[u][6] = p1.z; acc[u][7] = p1.w;
    }
    // + edge_attr @ W1_bot
    #pragma unroll 4
    for (int k = 0; k < EF; k++) {
        float av[8], wv[8];
        #pragma unroll
        for (int u = 0; u < 8; u++) av[u] = sEA[(eb + u) * EF + k];
        float4 w0 = *(const float4*)(sW1b + k * 128 + jb);
        float4 w1 = *(const float4*)(sW1b + k * 128 + jb + 4);
        wv[0] = w0.x; wv[1] = w0.y; wv[2] = w0.z; wv[3] = w0.w;
        wv[4] = w1.x; wv[5] = w1.y; wv[6] = w1.z; wv[7] = w1.w;
        #pragma unroll
        for (int u = 0; u < 8; u++)
            #pragma unroll
            for (int v = 0; v < 8; v++) acc[u][v] += av[u] * wv[v];
    }
    // relu -> sH
    #pragma unroll
    for (int u = 0; u < 8; u++) {
        float4 v0 = make_float4(fmaxf(acc[u][0], 0.f), fmaxf(acc[u][1], 0.f),
                                fmaxf(acc[u][2], 0.f), fmaxf(acc[u][3], 0.f));
        float4 v1 = make_float4(fmaxf(acc[u][4], 0.f), fmaxf(acc[u][5], 0.f),
                                fmaxf(acc[u][6], 0.f), fmaxf(acc[u][7], 0.f));
        *(float4*)(sH + (eb + u) * 128 + jb) = v0;
        *(float4*)(sH + (eb + u) * 128 + jb + 4) = v1;
    }
    __syncthreads();

    // msg = h @ W2 + b2
    {
        float4 b0 = *(const float4*)(b2 + jb);
        float4 b1v = *(const float4*)(b2 + jb + 4);
        #pragma unroll
        for (int u = 0; u < 8; u++) {
            acc[u][0] = b0.x;  acc[u][1] = b0.y;  acc[u][2] = b0.z;  acc[u][3] = b0.w;
            acc[u][4] = b1v.x; acc[u][5] = b1v.y; acc[u][6] = b1v.z; acc[u][7] = b1v.w;
        }
    }
    #pragma unroll 4
    for (int k = 0; k < 128; k++) {
        float av[8], wv[8];
        #pragma unroll
        for (int u = 0; u < 8; u++) av[u] = sH[(eb + u) * 128 + k];
        float4 w0 = *(const float4*)(sW2 + k * 128 + jb);
        float4 w1 = *(const float4*)(sW2 + k * 128 + jb + 4);
        wv[0] = w0.x; wv[1] = w0.y; wv[2] = w0.z; wv[3] = w0.w;
        wv[4] = w1.x; wv[5] = w1.y; wv[6] = w1.z; wv[7] = w1.w;
        #pragma unroll
        for (int u = 0; u < 8; u++)
            #pragma unroll
            for (int v = 0; v < 8; v++) acc[u][v] += av[u] * wv[v];
    }
    // scatter: vectorized float4 reductions (sm_90+ native, -> RED.E.ADD.F32X4)
    #pragma unroll
    for (int u = 0; u < 8; u++) {
        if (e0 + eb + u < E) {
            float* dst = g_sums + (size_t)s_row[eb + u] * 128 + jb;
            atomicAdd((float4*)dst,
                      make_float4(acc[u][0], acc[u][1], acc[u][2], acc[u][3]));
            atomicAdd((float4*)(dst + 4),
                      make_float4(acc[u][4], acc[u][5], acc[u][6], acc[u][7]));
        }
    }
    if (tid < 128 && e0 + tid < E) atomicAdd(&g_cnt[s_row[tid]], 1.0f);
}

// ---------------------------------------------------------------------------
// mean = sums / max(cnt,1); t = relu(P3 + mean @ W3_bot); out = t @ W4 + b4
__global__ __launch_bounds__(256, 1)
void node_kernel(const float* __restrict__ W3, const float* __restrict__ W4,
                 const float* __restrict__ b4, float* __restrict__ out) {
    extern __shared__ float sm[];
    float* sW = sm;              // 128*128 (W3_bot, then W4)
    float* sM = sm + 16384;      // mean tile
    float* sT = sm + 32768;      // relu output tile
    float* s_inv = sm + 49152;   // 128

    const int tid = threadIdx.x;
    const int m0 = blockIdx.x * 128;

    if (tid < 128) {
        int gm = m0 + tid;
        float c = (gm < N_NODES) ? g_cnt[gm] : 1.f;
        s_inv[tid] = 1.f / fmaxf(c, 1.f);
    }
    {   // W3_bot rows 128..255 (multiply mean)
        const float4* src = (const float4*)(W3 + 128 * 128);
        float4* dst = (float4*)sW;
        #pragma unroll
        for (int i = 0; i < 16; i++) dst[tid + 256 * i] = src[tid + 256 * i];
    }
    __syncthreads();
    for (int i = tid; i < 4096; i += 256) {
        int m = i >> 5;
        int k4 = (i & 31) << 2;
        int gm = m0 + m;
        float4 v = make_float4(0.f, 0.f, 0.f, 0.f);
        if (gm < N_NODES) {
            v = *(const float4*)(g_sums + (size_t)gm * 128 + k4);
            float s = s_inv[m];
            v.x *= s; v.y *= s; v.z *= s; v.w *= s;
        }
        *(float4*)(sM + m * 128 + k4) = v;
    }
    __syncthreads();

    const int tm = tid >> 4, tj = tid & 15;
    const int mb = tm * 8, jb = tj * 8;
    float acc[8][8];

    // init from P3 (b3 folded in)
    #pragma unroll
    for (int u = 0; u < 8; u++) {
        int gm = m0 + mb + u;
        if (gm < N_NODES) {
            const float* p = g_P3 + (size_t)gm * 128 + jb;
            float4 p0 = *(const float4*)p;
            float4 p1 = *(const float4*)(p + 4);
            acc[u][0] = p0.x; acc[u][1] = p0.y; acc[u][2] = p0.z; acc[u][3] = p0.w;
            acc[u][4] = p1.x; acc[u][5] = p1.y; acc[u][6] = p1.z; acc[u][7] = p1.w;
        } else {
            #pragma unroll
            for (int v = 0; v < 8; v++) acc[u][v] = 0.f;
        }
    }
    #pragma unroll 4
    for (int k = 0; k < 128; k++) {
        float av[8], wv[8];
        #pragma unroll
        for (int u = 0; u < 8; u++) av[u] = sM[(mb + u) * 128 + k];
        float4 w0 = *(const float4*)(sW + k * 128 + jb);
        float4 w1 = *(const float4*)(sW + k * 128 + jb + 4);
        wv[0] = w0.x; wv[1] = w0.y; wv[2] = w0.z; wv[3] = w0.w;
        wv[4] = w1.x; wv[5] = w1.y; wv[6] = w1.z; wv[7] = w1.w;
        #pragma unroll
        for (int u = 0; u < 8; u++)
            #pragma unroll
            for (int v = 0; v < 8; v++) acc[u][v] += av[u] * wv[v];
    }
    #pragma unroll
    for (int u = 0; u < 8; u++) {
        float4 v0 = make_float4(fmaxf(acc[u][0], 0.f), fmaxf(acc[u][1], 0.f),
                                fmaxf(acc[u][2], 0.f), fmaxf(acc[u][3], 0.f));
        float4 v1 = make_float4(fmaxf(acc[u][4], 0.f), fmaxf(acc[u][5], 0.f),
                                fmaxf(acc[u][6], 0.f), fmaxf(acc[u][7], 0.f));
        *(float4*)(sT + (mb + u) * 128 + jb) = v0;
        *(float4*)(sT + (mb + u) * 128 + jb + 4) = v1;
    }
    __syncthreads();
    {   // swap weights to W4
        const float4* src = (const float4*)W4;
        float4* dst = (float4*)sW;
        #pragma unroll
        for (int i = 0; i < 16; i++) dst[tid + 256 * i] = src[tid + 256 * i];
    }
    __syncthreads();
    {
        float4 b0 = *(const float4*)(b4 + jb);
        float4 b1v = *(const float4*)(b4 + jb + 4);
        #pragma unroll
        for (int u = 0; u < 8; u++) {
            acc[u][0] = b0.x;  acc[u][1] = b0.y;  acc[u][2] = b0.z;  acc[u][3] = b0.w;
            acc[u][4] = b1v.x; acc[u][5] = b1v.y; acc[u][6] = b1v.z; acc[u][7] = b1v.w;
        }
    }
    #pragma unroll 4
    for (int k = 0; k < 128; k++) {
        float av[8], wv[8];
        #pragma unroll
        for (int u = 0; u < 8; u++) av[u] = sT[(mb + u) * 128 + k];
        float4 w0 = *(const float4*)(sW + k * 128 + jb);
        float4 w1 = *(const float4*)(sW + k * 128 + jb + 4);
        wv[0] = w0.x; wv[1] = w0.y; wv[2] = w0.z; wv[3] = w0.w;
        wv[4] = w1.x; wv[5] = w1.y; wv[6] = w1.z; wv[7] = w1.w;
        #pragma unroll
        for (int u = 0; u < 8; u++)
            #pragma unroll
            for (int v = 0; v < 8; v++) acc[u][v] += av[u] * wv[v];
    }
    #pragma unroll
    for (int u = 0; u < 8; u++) {
        int gm = m0 + mb + u;
        if (gm < N_NODES) {
            *(float4*)(out + (size_t)gm * 128 + jb) =
                make_float4(acc[u][0], acc[u][1], acc[u][2], acc[u][3]);
            *(float4*)(out + (size_t)gm * 128 + jb + 4) =
                make_float4(acc[u][4], acc[u][5], acc[u][6], acc[u][7]);
        }
    }
}

// ---------------------------------------------------------------------------
extern "C" void kernel_launch(void* const* d_in, const int* in_sizes, int n_in,
                              void* d_out, int out_size) {
    const float* node_feat = (const float*)d_in[0];
    const int*   eidx      = (const int*)d_in[1];   // int32 (JAX x64 disabled)
    const float* ea        = (const float*)d_in[2];
    const float* W1 = (const float*)d_in[3];
    const float* b1 = (const float*)d_in[4];
    const float* W2 = (const float*)d_in[5];
    const float* b2 = (const float*)d_in[6];
    const float* W3 = (const float*)d_in[7];
    const float* b3 = (const float*)d_in[8];
    const float* W4 = (const float*)d_in[9];
    const float* b4 = (const float*)d_in[10];
    float* out = (float*)d_out;

    const int E = in_sizes[1] / 2;

    const int PRE_SMEM  = 2 * 128 * 128 * 4;            // 128 KB
    const int EDGE_SMEM = 49152 * 4 + 1024;             // ~193 KB
    const int NODE_SMEM = 49152 * 4 + 512;              // ~192.5 KB
    cudaFuncSetAttribute(pre_kernel,  cudaFuncAttributeMaxDynamicSharedMemorySize, PRE_SMEM);
    cudaFuncSetAttribute(edge_kernel, cudaFuncAttributeMaxDynamicSharedMemorySize, EDGE_SMEM);
    cudaFuncSetAttribute(node_kernel, cudaFuncAttributeMaxDynamicSharedMemorySize, NODE_SMEM);

    const int NBN = (N_NODES + 127) / 128;  // 391
    const int NBE = (E + 127) / 128;        // 12500

    zero_kernel<<<1024, 256>>>();
    pre_kernel<<<NBN, 256, PRE_SMEM>>>(node_feat, W1, b1, 0);
    pre_kernel<<<NBN, 256, PRE_SMEM>>>(node_feat, W3, b3, 1);
    edge_kernel<<<NBE, 256, EDGE_SMEM>>>(ea, eidx, W1, W2, b2, E);
    node_kernel<<<NBN, 256, NODE_SMEM>>>(W3, W4, b4, out);
}

// round 4
// speedup vs baseline: 1.9343x; 1.9343x over previous
#include <cuda_runtime.h>
#include <cuda_bf16.h>
#include <cstdint>

#define N_NODES 50000
#define HID 128
#define EF 64

// ---------------------------------------------------------------------------
// Scratch (device globals — allocation-free per harness rules)
__device__ float g_P   [(size_t)N_NODES * HID];   // node_feat @ W1_top + b1
__device__ float g_P3  [(size_t)N_NODES * HID];   // node_feat @ W3_top + b3
__device__ float g_sums[(size_t)N_NODES * HID];   // scatter-add target (no b2)
__device__ float g_cnt [N_NODES];
// Pre-split bf16 weight images, transposed to [N][K] K-major rows of 128B,
// SW128-swizzled: [B1hi 16K][B1lo 16K][B2hi0][B2hi1][B2lo0][B2lo1]
__device__ __align__(16) unsigned char g_WB[6 * 16384];

__device__ __forceinline__ uint32_t smem_u32(const void* p) {
    uint32_t a;
    asm("{ .reg .u64 t; cvta.to.shared.u64 t, %1; cvt.u32.u64 %0, t; }"
        : "=r"(a) : "l"(p));
    return a;
}
__device__ __forceinline__ uint32_t swz(uint32_t b) { return b ^ ((b >> 3) & 0x70); }

__device__ __forceinline__ void ldsm_x4(uint32_t* r, uint32_t addr) {
    asm volatile("ldmatrix.sync.aligned.m8n8.x4.shared.b16 {%0,%1,%2,%3}, [%4];"
                 : "=r"(r[0]), "=r"(r[1]), "=r"(r[2]), "=r"(r[3]) : "r"(addr));
}
__device__ __forceinline__ void ldsm_x2(uint32_t* r, uint32_t addr) {
    asm volatile("ldmatrix.sync.aligned.m8n8.x2.shared.b16 {%0,%1}, [%2];"
                 : "=r"(r[0]), "=r"(r[1]) : "r"(addr));
}
__device__ __forceinline__ void mma_bf16(float* d, const uint32_t* a, const uint32_t* b) {
    asm volatile("mma.sync.aligned.m16n8k16.row.col.f32.bf16.bf16.f32 "
                 "{%0,%1,%2,%3}, {%4,%5,%6,%7}, {%8,%9}, {%0,%1,%2,%3};"
                 : "+f"(d[0]), "+f"(d[1]), "+f"(d[2]), "+f"(d[3])
                 : "r"(a[0]), "r"(a[1]), "r"(a[2]), "r"(a[3]), "r"(b[0]), "r"(b[1]));
}
__device__ __forceinline__ uint32_t pack_bf16x2(float x, float y) {
    __nv_bfloat162 p = {__float2bfloat16(x), __float2bfloat16(y)};
    return *(uint32_t*)&p;
}

// ---------------------------------------------------------------------------
__global__ void zero_kernel() {
    const size_t total4 = (size_t)N_NODES * HID / 4;
    float4* s = (float4*)g_sums;
    const float4 z = make_float4(0.f, 0.f, 0.f, 0.f);
    for (size_t i = (size_t)blockIdx.x * blockDim.x + threadIdx.x; i < total4;
         i += (size_t)gridDim.x * blockDim.x)
        s[i] = z;
    for (int i = blockIdx.x * blockDim.x + threadIdx.x; i < N_NODES;
         i += gridDim.x * blockDim.x)
        g_cnt[i] = 0.f;
}

// ---------------------------------------------------------------------------
// Split W1_bot (rows 128..191 of W1) and W2 into bf16 hi/lo, [N][K] K-major,
// 128B rows, SW128-swizzled — the exact SMEM byte image edge CTAs copy.
__global__ void prep_weights(const float* __restrict__ W1,
                             const float* __restrict__ W2) {
    const int tid = blockIdx.x * blockDim.x + threadIdx.x;
    const int nth = gridDim.x * blockDim.x;
    for (int i = tid; i < 128 * 64; i += nth) {
        int n = i >> 6, k = i & 63;
        float v = W1[(128 + k) * 128 + n];
        __nv_bfloat16 h = __float2bfloat16(v);
        __nv_bfloat16 l = __float2bfloat16(v - __bfloat162float(h));
        uint32_t off = swz(n * 128 + k * 2);
        *(__nv_bfloat16*)(g_WB + off)         = h;
        *(__nv_bfloat16*)(g_WB + 16384 + off) = l;
    }
    for (int i = tid; i < 128 * 128; i += nth) {
        int n = i >> 7, kcol = i & 127;
        int c = kcol >> 6, kk = kcol & 63;
        float v = W2[kcol * 128 + n];
        __nv_bfloat16 h = __float2bfloat16(v);
        __nv_bfloat16 l = __float2bfloat16(v - __bfloat162float(h));
        uint32_t off = swz(n * 128 + kk * 2);
        *(__nv_bfloat16*)(g_WB + 32768 + c * 16384 + off) = h;
        *(__nv_bfloat16*)(g_WB + 65536 + c * 16384 + off) = l;
    }
}

// ---------------------------------------------------------------------------
// Generic C = A @ W + b (node-side precompute), SIMT fp32.
__global__ __launch_bounds__(256, 1)
void pre_kernel(const float* __restrict__ A, const float* __restrict__ W,
                const float* __restrict__ b, int which) {
    extern __shared__ float sm[];
    float* sW = sm;
    float* sA = sm + 128 * 128;
    float* C = which ? g_P3 : g_P;

    const int tid = threadIdx.x;
    const int m0 = blockIdx.x * 128;

    {
        const float4* src = (const float4*)W;
        float4* dst = (float4*)sW;
        #pragma unroll
        for (int i = 0; i < 16; i++) dst[tid + 256 * i] = src[tid + 256 * i];
    }
    for (int i = tid; i < 4096; i += 256) {
        int m = i >> 5, k4 = (i & 31) << 2, gm = m0 + m;
        float4 v = make_float4(0.f, 0.f, 0.f, 0.f);
        if (gm < N_NODES) v = *(const float4*)(A + (size_t)gm * 128 + k4);
        *(float4*)(sA + m * 128 + k4) = v;
    }
    __syncthreads();

    const int tm = tid >> 4, tj = tid & 15;
    const int mb = tm * 8, jb = tj * 8;
    float acc[8][8];
    {
        float4 b0 = *(const float4*)(b + jb);
        float4 b1v = *(const float4*)(b + jb + 4);
        #pragma unroll
        for (int u = 0; u < 8; u++) {
            acc[u][0] = b0.x;  acc[u][1] = b0.y;  acc[u][2] = b0.z;  acc[u][3] = b0.w;
            acc[u][4] = b1v.x; acc[u][5] = b1v.y; acc[u][6] = b1v.z; acc[u][7] = b1v.w;
        }
    }
    #pragma unroll 4
    for (int k = 0; k < 128; k++) {
        float av[8], wv[8];
        #pragma unroll
        for (int u = 0; u < 8; u++) av[u] = sA[(mb + u) * 128 + k];
        float4 w0 = *(const float4*)(sW + k * 128 + jb);
        float4 w1 = *(const float4*)(sW + k * 128 + jb + 4);
        wv[0] = w0.x; wv[1] = w0.y; wv[2] = w0.z; wv[3] = w0.w;
        wv[4] = w1.x; wv[5] = w1.y; wv[6] = w1.z; wv[7] = w1.w;
        #pragma unroll
        for (int u = 0; u < 8; u++)
            #pragma unroll
            for (int v = 0; v < 8; v++) acc[u][v] += av[u] * wv[v];
    }
    #pragma unroll
    for (int u = 0; u < 8; u++) {
        int gm = m0 + mb + u;
        if (gm < N_NODES) {
            *(float4*)(C + (size_t)gm * 128 + jb) =
                make_float4(acc[u][0], acc[u][1], acc[u][2], acc[u][3]);
            *(float4*)(C + (size_t)gm * 128 + jb + 4) =
                make_float4(acc[u][4], acc[u][5], acc[u][6], acc[u][7]);
        }
    }
}

// ---------------------------------------------------------------------------
// Tensor-core edge kernel (mma.sync bf16x3 fp32-emulation). Persistent grid.
// SMEM map (bytes):
//  0 B1hi | 16K B1lo | 32K B2hi(2ch) | 64K B2lo(2ch)
//  96K AHI | 112K ALO | 128K HHI(2ch) | 160K HLO(2ch)
//  96K..160K reused as MSG float[128][128] after GEMM2
//  192K s_row[128], s_col[128]
#define SM_B1HI  0
#define SM_B1LO  16384
#define SM_B2HI  32768
#define SM_B2LO  65536
#define SM_AHI   98304
#define SM_ALO   114688
#define SM_HHI   131072
#define SM_HLO   163840
#define SM_MSG   98304
#define SM_IDX   196608
#define EDGE_SMEM_BYTES (196608 + 1024)

__global__ __launch_bounds__(256, 1)
void edge_kernel_mma(const float* __restrict__ ea, const int* __restrict__ eidx,
                     int E, int ntiles) {
    extern __shared__ char smc[];
    const uint32_t smb = smem_u32(smc);
    const int tid = threadIdx.x;
    const int wid = tid >> 5;
    const int lid = tid & 31;

    int* s_row = (int*)(smc + SM_IDX);
    int* s_col = s_row + 128;

    // weights: linear copy of pre-swizzled image (96 KB) once
    {
        const float4* src = (const float4*)g_WB;
        float4* dst = (float4*)smc;
        for (int i = tid; i < 6144; i += 256) dst[i] = src[i];
    }

    // per-lane fragment geometry
    const int wr0 = wid * 16;                 // warp's row strip
    const int qr  = lid >> 2;                 // 0..7
    const int qc  = (lid & 3) * 2;            // 0,2,4,6
    const int r0  = wr0 + qr, r1 = r0 + 8;    // fragment rows (tile-relative)
    // ldmatrix A-side lane address components (row fixed per lane)
    const int am   = lid >> 3;                                   // 0..3
    const int arow = wr0 + ((am & 1) << 3) + (lid & 7);
    const int akof = (am >> 1) << 4;                              // 0 or 16 bytes
    // ldmatrix B-side lane address components
    const int brow = lid & 7;
    const int bkof = ((lid >> 3) & 1) << 4;

    for (int tile = blockIdx.x; tile < ntiles; tile += gridDim.x) {
        const int e0 = tile * 128;

        // ---- stage indices + edge_attr (fp32 -> bf16 hi/lo, swizzled) ----
        if (tid < 128) {
            int e = e0 + tid;
            s_row[tid] = (e < E) ? eidx[e] : 0;
        } else {
            int t = tid - 128, e = e0 + t;
            s_col[t] = (e < E) ? eidx[(size_t)E + e] : 0;
        }
        {
            const int r = tid >> 1;
            const int cb = (tid & 1) * 32;
            const int e = e0 + r;
            const float* src = ea + (size_t)e * EF + cb;
            #pragma unroll
            for (int j = 0; j < 8; j++) {
                float4 v = (e < E) ? *(const float4*)(src + j * 4)
                                   : make_float4(0.f, 0.f, 0.f, 0.f);
                __nv_bfloat16 h0 = __float2bfloat16(v.x), h1 = __float2bfloat16(v.y);
                __nv_bfloat16 h2 = __float2bfloat16(v.z), h3 = __float2bfloat16(v.w);
                uint32_t hi0 = pack_bf16x2(v.x, v.y), hi1 = pack_bf16x2(v.z, v.w);
                uint32_t lo0 = pack_bf16x2(v.x - __bfloat162float(h0),
                                           v.y - __bfloat162float(h1));
                uint32_t lo1 = pack_bf16x2(v.z - __bfloat162float(h2),
                                           v.w - __bfloat162float(h3));
                uint32_t off = swz(r * 128 + (cb + j * 4) * 2);
                *(uint2*)(smc + SM_AHI + off) = make_uint2(hi0, hi1);
                *(uint2*)(smc + SM_ALO + off) = make_uint2(lo0, lo1);
            }
        }
        __syncthreads();

        float acc[16][4];
        #pragma unroll
        for (int nt = 0; nt < 16; nt++)
            #pragma unroll
            for (int v = 0; v < 4; v++) acc[nt][v] = 0.f;

        // ---- GEMM1: D1 = EA @ W1_bot (bf16x3), K=64 ----
        #pragma unroll
        for (int kt = 0; kt < 4; kt++) {
            const int kb = kt * 32;
            uint32_t ahi[4], alo[4];
            ldsm_x4(ahi, smb + SM_AHI + swz(arow * 128 + kb + akof));
            ldsm_x4(alo, smb + SM_ALO + swz(arow * 128 + kb + akof));
            #pragma unroll
            for (int nt = 0; nt < 16; nt++) {
                uint32_t bo = swz((nt * 8 + brow) * 128 + kb + bkof);
                uint32_t bhi[2], blo[2];
                ldsm_x2(bhi, smb + SM_B1HI + bo);
                ldsm_x2(blo, smb + SM_B1LO + bo);
                mma_bf16(acc[nt], ahi, bhi);
                mma_bf16(acc[nt], ahi, blo);
                mma_bf16(acc[nt], alo, bhi);
            }
        }

        // ---- epilogue 1: h = relu(D1 + P[col]); split hi/lo -> SMEM H ----
        {
            const float* P0 = g_P + (size_t)s_col[r0] * 128;
            const float* P1 = g_P + (size_t)s_col[r1] * 128;
            #pragma unroll
            for (int nt = 0; nt < 16; nt++) {
                const int c = nt * 8 + qc;
                float2 p0 = *(const float2*)(P0 + c);
                float2 p1 = *(const float2*)(P1 + c);
                float h00 = fmaxf(acc[nt][0] + p0.x, 0.f);
                float h01 = fmaxf(acc[nt][1] + p0.y, 0.f);
                float h10 = fmaxf(acc[nt][2] + p1.x, 0.f);
                float h11 = fmaxf(acc[nt][3] + p1.y, 0.f);
                uint32_t hi0 = pack_bf16x2(h00, h01);
                uint32_t hi1 = pack_bf16x2(h10, h11);
                __nv_bfloat162* t0 = (__nv_bfloat162*)&hi0;
                __nv_bfloat162* t1 = (__nv_bfloat162*)&hi1;
                uint32_t lo0 = pack_bf16x2(h00 - __bfloat162float(t0->x),
                                           h01 - __bfloat162float(t0->y));
                uint32_t lo1 = pack_bf16x2(h10 - __bfloat162float(t1->x),
                                           h11 - __bfloat162float(t1->y));
                const int chunk = (c >> 6) * 16384;
                const int kk2 = (c & 63) * 2;
                uint32_t o0 = swz(r0 * 128 + kk2), o1 = swz(r1 * 128 + kk2);
                *(uint32_t*)(smc + SM_HHI + chunk + o0) = hi0;
                *(uint32_t*)(smc + SM_HHI + chunk + o1) = hi1;
                *(uint32_t*)(smc + SM_HLO + chunk + o0) = lo0;
                *(uint32_t*)(smc + SM_HLO + chunk + o1) = lo1;
            }
        }
        __syncthreads();

        // ---- GEMM2: D2 = H @ W2 (bf16x3), K=128 ----
        #pragma unroll
        for (int nt = 0; nt < 16; nt++)
            #pragma unroll
            for (int v = 0; v < 4; v++) acc[nt][v] = 0.f;
        #pragma unroll
        for (int kt = 0; kt < 8; kt++) {
            const int chunk = (kt >> 2) * 16384;
            const int kb = (kt & 3) * 32;
            uint32_t ahi[4], alo[4];
            ldsm_x4(ahi, smb + SM_HHI + chunk + swz(arow * 128 + kb + akof));
            ldsm_x4(alo, smb + SM_HLO + chunk + swz(arow * 128 + kb + akof));
            #pragma unroll
            for (int nt = 0; nt < 16; nt++) {
                uint32_t bo = swz((nt * 8 + brow) * 128 + kb + bkof);
                uint32_t bhi[2], blo[2];
                ldsm_x2(bhi, smb + SM_B2HI + chunk + bo);
                ldsm_x2(blo, smb + SM_B2LO + chunk + bo);
                mma_bf16(acc[nt], ahi, bhi);
                mma_bf16(acc[nt], ahi, blo);
                mma_bf16(acc[nt], alo, bhi);
            }
        }
        __syncthreads();   // all warps done reading H before MSG overwrites it

        // ---- epilogue 2: fragments -> MSG (rotated rows to dodge conflicts) ----
        {
            float* msg = (float*)(smc + SM_MSG);
            const int rot0 = (r0 & 15) * 8, rot1 = (r1 & 15) * 8;
            #pragma unroll
            for (int nt = 0; nt < 16; nt++) {
                const int c = nt * 8 + qc;
                *(float2*)(msg + r0 * 128 + ((c + rot0) & 127)) =
                    make_float2(acc[nt][0], acc[nt][1]);
                *(float2*)(msg + r1 * 128 + ((c + rot1) & 127)) =
                    make_float2(acc[nt][2], acc[nt][3]);
            }
        }
        __syncthreads();

        // ---- scatter: atomicAdd float4 into g_sums ----
        {
            const int r = tid >> 1;
            const int half = (tid & 1) * 64;
            if (e0 + r < E) {
                const float* msg = (const float*)(smc + SM_MSG) + r * 128;
                const int rot = (r & 15) * 8;
                float* dst = g_sums + (size_t)s_row[r] * 128 + half;
                #pragma unroll
                for (int j = 0; j < 16; j++) {
                    const int c = half + j * 4;
                    float4 v = *(const float4*)(msg + ((c + rot) & 127));
                    atomicAdd((float4*)(dst + j * 4), v);
                }
            }
        }
        if (tid < 128 && e0 + tid < E) atomicAdd(&g_cnt[s_row[tid]], 1.0f);
        __syncthreads();   // protect MSG/A region + s_row/s_col before next tile
    }
}

// ---------------------------------------------------------------------------
// mean = sums/max(cnt,1) + b2*[cnt>0]; t = relu(P3 + mean @ W3_bot);
// out = t @ W4 + b4
__global__ __launch_bounds__(256, 1)
void node_kernel(const float* __restrict__ W3, const float* __restrict__ W4,
                 const float* __restrict__ b4, const float* __restrict__ b2,
                 float* __restrict__ out) {
    extern __shared__ float sm[];
    float* sW = sm;
    float* sM = sm + 16384;
    float* sT = sm + 32768;
    float* s_inv  = sm + 49152;   // 128
    float* s_flag = sm + 49280;   // 128
    float* s_b2   = sm + 49408;   // 128

    const int tid = threadIdx.x;
    const int m0 = blockIdx.x * 128;

    if (tid < 128) {
        int gm = m0 + tid;
        float c = (gm < N_NODES) ? g_cnt[gm] : 0.f;
        s_inv[tid] = 1.f / fmaxf(c, 1.f);
        s_flag[tid] = (c > 0.f) ? 1.f : 0.f;
        s_b2[tid] = b2[tid];
    }
    {
        const float4* src = (const float4*)(W3 + 128 * 128);
        float4* dst = (float4*)sW;
        #pragma unroll
        for (int i = 0; i < 16; i++) dst[tid + 256 * i] = src[tid + 256 * i];
    }
    __syncthreads();
    for (int i = tid; i < 4096; i += 256) {
        int m = i >> 5, k4 = (i & 31) << 2, gm = m0 + m;
        float4 v = make_float4(0.f, 0.f, 0.f, 0.f);
        if (gm < N_NODES) {
            v = *(const float4*)(g_sums + (size_t)gm * 128 + k4);
            float s = s_inv[m], f = s_flag[m];
            v.x = v.x * s + f * s_b2[k4];
            v.y = v.y * s + f * s_b2[k4 + 1];
            v.z = v.z * s + f * s_b2[k4 + 2];
            v.w = v.w * s + f * s_b2[k4 + 3];
        }
        *(float4*)(sM + m * 128 + k4) = v;
    }
    __syncthreads();

    const int tm = tid >> 4, tj = tid & 15;
    const int mb = tm * 8, jb = tj * 8;
    float acc[8][8];

    #pragma unroll
    for (int u = 0; u < 8; u++) {
        int gm = m0 + mb + u;
        if (gm < N_NODES) {
            const float* p = g_P3 + (size_t)gm * 128 + jb;
            float4 p0 = *(const float4*)p;
            float4 p1 = *(const float4*)(p + 4);
            acc[u][0] = p0.x; acc[u][1] = p0.y; acc[u][2] = p0.z; acc[u][3] = p0.w;
            acc[u][4] = p1.x; acc[u][5] = p1.y; acc[u][6] = p1.z; acc[u][7] = p1.w;
        } else {
            #pragma unroll
            for (int v = 0; v < 8; v++) acc[u][v] = 0.f;
        }
    }
    #pragma unroll 4
    for (int k = 0; k < 128; k++) {
        float av[8], wv[8];
        #pragma unroll
        for (int u = 0; u < 8; u++) av[u] = sM[(mb + u) * 128 + k];
        float4 w0 = *(const float4*)(sW + k * 128 + jb);
        float4 w1 = *(const float4*)(sW + k * 128 + jb + 4);
        wv[0] = w0.x; wv[1] = w0.y; wv[2] = w0.z; wv[3] = w0.w;
        wv[4] = w1.x; wv[5] = w1.y; wv[6] = w1.z; wv[7] = w1.w;
        #pragma unroll
        for (int u = 0; u < 8; u++)
            #pragma unroll
            for (int v = 0; v < 8; v++) acc[u][v] += av[u] * wv[v];
    }
    #pragma unroll
    for (int u = 0; u < 8; u++) {
        float4 v0 = make_float4(fmaxf(acc[u][0], 0.f), fmaxf(acc[u][1], 0.f),
                                fmaxf(acc[u][2], 0.f), fmaxf(acc[u][3], 0.f));
        float4 v1 = make_float4(fmaxf(acc[u][4], 0.f), fmaxf(acc[u][5], 0.f),
                                fmaxf(acc[u][6], 0.f), fmaxf(acc[u][7], 0.f));
        *(float4*)(sT + (mb + u) * 128 + jb) = v0;
        *(float4*)(sT + (mb + u) * 128 + jb + 4) = v1;
    }
    __syncthreads();
    {
        const float4* src = (const float4*)W4;
        float4* dst = (float4*)sW;
        #pragma unroll
        for (int i = 0; i < 16; i++) dst[tid + 256 * i] = src[tid + 256 * i];
    }
    __syncthreads();
    {
        float4 b0 = *(const float4*)(b4 + jb);
        float4 b1v = *(const float4*)(b4 + jb + 4);
        #pragma unroll
        for (int u = 0; u < 8; u++) {
            acc[u][0] = b0.x;  acc[u][1] = b0.y;  acc[u][2] = b0.z;  acc[u][3] = b0.w;
            acc[u][4] = b1v.x; acc[u][5] = b1v.y; acc[u][6] = b1v.z; acc[u][7] = b1v.w;
        }
    }
    #pragma unroll 4
    for (int k = 0; k < 128; k++) {
        float av[8], wv[8];
        #pragma unroll
        for (int u = 0; u < 8; u++) av[u] = sT[(mb + u) * 128 + k];
        float4 w0 = *(const float4*)(sW + k * 128 + jb);
        float4 w1 = *(const float4*)(sW + k * 128 + jb + 4);
        wv[0] = w0.x; wv[1] = w0.y; wv[2] = w0.z; wv[3] = w0.w;
        wv[4] = w1.x; wv[5] = w1.y; wv[6] = w1.z; wv[7] = w1.w;
        #pragma unroll
        for (int u = 0; u < 8; u++)
            #pragma unroll
            for (int v = 0; v < 8; v++) acc[u][v] += av[u] * wv[v];
    }
    #pragma unroll
    for (int u = 0; u < 8; u++) {
        int gm = m0 + mb + u;
        if (gm < N_NODES) {
            *(float4*)(out + (size_t)gm * 128 + jb) =
                make_float4(acc[u][0], acc[u][1], acc[u][2], acc[u][3]);
            *(float4*)(out + (size_t)gm * 128 + jb + 4) =
                make_float4(acc[u][4], acc[u][5], acc[u][6], acc[u][7]);
        }
    }
}

// ---------------------------------------------------------------------------
extern "C" void kernel_launch(void* const* d_in, const int* in_sizes, int n_in,
                              void* d_out, int out_size) {
    const float* node_feat = (const float*)d_in[0];
    const int*   eidx      = (const int*)d_in[1];   // int32 (JAX x64 disabled)
    const float* ea        = (const float*)d_in[2];
    const float* W1 = (const float*)d_in[3];
    const float* b1 = (const float*)d_in[4];
    const float* W2 = (const float*)d_in[5];
    const float* b2 = (const float*)d_in[6];
    const float* W3 = (const float*)d_in[7];
    const float* b3 = (const float*)d_in[8];
    const float* W4 = (const float*)d_in[9];
    const float* b4 = (const float*)d_in[10];
    float* out = (float*)d_out;

    const int E = in_sizes[1] / 2;
    const int NBN = (N_NODES + 127) / 128;   // 391
    const int NBE = (E + 127) / 128;         // 12500

    const int PRE_SMEM  = 2 * 128 * 128 * 4;
    const int NODE_SMEM = 49152 * 4 + 3 * 128 * 4;
    cudaFuncSetAttribute(pre_kernel, cudaFuncAttributeMaxDynamicSharedMemorySize, PRE_SMEM);
    cudaFuncSetAttribute(edge_kernel_mma, cudaFuncAttributeMaxDynamicSharedMemorySize, EDGE_SMEM_BYTES);
    cudaFuncSetAttribute(node_kernel, cudaFuncAttributeMaxDynamicSharedMemorySize, NODE_SMEM);

    zero_kernel<<<1024, 256>>>();
    prep_weights<<<64, 256>>>(W1, W2);
    pre_kernel<<<NBN, 256, PRE_SMEM>>>(node_feat, W1, b1, 0);
    pre_kernel<<<NBN, 256, PRE_SMEM>>>(node_feat, W3, b3, 1);
    edge_kernel_mma<<<148, 256, EDGE_SMEM_BYTES>>>(ea, eidx, E, NBE);
    node_kernel<<<NBN, 256, NODE_SMEM>>>(W3, W4, b4, b2, out);
}

// round 5
// speedup vs baseline: 2.8070x; 1.4511x over previous
#include <cuda_runtime.h>
#include <cuda_bf16.h>
#include <cstdint>

#define N_NODES 50000
#define HID 128
#define EF 64

// ---------------------------------------------------------------------------
// Scratch (device globals — allocation-free per harness rules)
__device__ float g_P   [(size_t)N_NODES * HID];   // node_feat@W1_top+b1; reused as T after edge
__device__ float g_P3  [(size_t)N_NODES * HID];   // node_feat@W3_top+b3
__device__ float g_sums[(size_t)N_NODES * HID];   // scatter-add of relu-h
__device__ float g_cnt [N_NODES];
__device__ float g_W23 [128 * 128];               // W2 @ W3_bot (fp32)
__device__ float g_b23 [128];                     // b2 @ W3_bot
// bf16 hi/lo weight images, [N][K] K-major 128B rows, SW128-swizzled.
// [0,16K) B1hi | [16K,32K) B1lo | then 4 node weights x 64KB each:
//   base+0 hi c0 | +16K hi c1 | +32K lo c0 | +48K lo c1
__device__ __align__(16) unsigned char g_WB[32768 + 4 * 65536];

__device__ __forceinline__ uint32_t smem_u32(const void* p) {
    uint32_t a;
    asm("{ .reg .u64 t; cvta.to.shared.u64 t, %1; cvt.u32.u64 %0, t; }"
        : "=r"(a) : "l"(p));
    return a;
}
__device__ __forceinline__ uint32_t swz(uint32_t b) { return b ^ ((b >> 3) & 0x70); }

__device__ __forceinline__ void ldsm_x4(uint32_t* r, uint32_t addr) {
    asm volatile("ldmatrix.sync.aligned.m8n8.x4.shared.b16 {%0,%1,%2,%3}, [%4];"
                 : "=r"(r[0]), "=r"(r[1]), "=r"(r[2]), "=r"(r[3]) : "r"(addr));
}
__device__ __forceinline__ void ldsm_x2(uint32_t* r, uint32_t addr) {
    asm volatile("ldmatrix.sync.aligned.m8n8.x2.shared.b16 {%0,%1}, [%2];"
                 : "=r"(r[0]), "=r"(r[1]) : "r"(addr));
}
__device__ __forceinline__ void mma_bf16(float* d, const uint32_t* a, const uint32_t* b) {
    asm volatile("mma.sync.aligned.m16n8k16.row.col.f32.bf16.bf16.f32 "
                 "{%0,%1,%2,%3}, {%4,%5,%6,%7}, {%8,%9}, {%0,%1,%2,%3};"
                 : "+f"(d[0]), "+f"(d[1]), "+f"(d[2]), "+f"(d[3])
                 : "r"(a[0]), "r"(a[1]), "r"(a[2]), "r"(a[3]), "r"(b[0]), "r"(b[1]));
}
__device__ __forceinline__ uint32_t pack_bf16x2(float x, float y) {
    __nv_bfloat162 p = {__float2bfloat16(x), __float2bfloat16(y)};
    return *(uint32_t*)&p;
}
// split fp32 pair -> (hi bf16x2, lo bf16x2)
__device__ __forceinline__ void split2(float x, float y, uint32_t& hi, uint32_t& lo) {
    __nv_bfloat16 hx = __float2bfloat16(x), hy = __float2bfloat16(y);
    __nv_bfloat162 ph = {hx, hy};
    hi = *(uint32_t*)&ph;
    lo = pack_bf16x2(x - __bfloat162float(hx), y - __bfloat162float(hy));
}

// ---------------------------------------------------------------------------
__global__ void zero_kernel() {
    const size_t total4 = (size_t)N_NODES * HID / 4;
    float4* s = (float4*)g_sums;
    const float4 z = make_float4(0.f, 0.f, 0.f, 0.f);
    for (size_t i = (size_t)blockIdx.x * blockDim.x + threadIdx.x; i < total4;
         i += (size_t)gridDim.x * blockDim.x)
        s[i] = z;
    for (int i = blockIdx.x * blockDim.x + threadIdx.x; i < N_NODES;
         i += gridDim.x * blockDim.x)
        g_cnt[i] = 0.f;
}

// ---------------------------------------------------------------------------
// W23 = W2 @ W3[128:256], b23 = b2 @ W3[128:256]  (fp32, exact-ish)
__global__ void prep1_kernel(const float* __restrict__ W2,
                             const float* __restrict__ W3,
                             const float* __restrict__ b2) {
    __shared__ float srow[128];
    const int r = blockIdx.x;     // 0..128 (128 == b23 row)
    const int c = threadIdx.x;    // 0..127
    srow[c] = (r < 128) ? W2[r * 128 + c] : b2[c];
    __syncthreads();
    float acc = 0.f;
    #pragma unroll 4
    for (int k = 0; k < 128; k++)
        acc += srow[k] * W3[(128 + k) * 128 + c];
    if (r < 128) g_W23[r * 128 + c] = acc;
    else         g_b23[c] = acc;
}

// ---------------------------------------------------------------------------
// Split weights into bf16 hi/lo swizzled images.
// Edge B1 = W1 rows 128..191 (edge_attr part). Node widx: 0=W1_top, 1=W3_top,
// 2=W23, 3=W4. Image value(n,k) = SRC[k*128 + n].
__global__ void prep2_kernel(const float* __restrict__ W1,
                             const float* __restrict__ W3,
                             const float* __restrict__ W4) {
    const int tid = blockIdx.x * blockDim.x + threadIdx.x;
    const int nth = gridDim.x * blockDim.x;
    for (int i = tid; i < 128 * 64; i += nth) {       // edge B1
        int n = i >> 6, k = i & 63;
        float v = W1[(128 + k) * 128 + n];
        __nv_bfloat16 h = __float2bfloat16(v);
        __nv_bfloat16 l = __float2bfloat16(v - __bfloat162float(h));
        uint32_t off = swz(n * 128 + k * 2);
        *(__nv_bfloat16*)(g_WB + off)         = h;
        *(__nv_bfloat16*)(g_WB + 16384 + off) = l;
    }
    for (int i = tid; i < 4 * 128 * 128; i += nth) {  // node weights
        int widx = i >> 14, j = i & 16383;
        int n = j >> 7, k = j & 127;
        float v;
        if      (widx == 0) v = W1[k * 128 + n];
        else if (widx == 1) v = W3[k * 128 + n];
        else if (widx == 2) v = g_W23[k * 128 + n];
        else                v = W4[k * 128 + n];
        __nv_bfloat16 h = __float2bfloat16(v);
        __nv_bfloat16 l = __float2bfloat16(v - __bfloat162float(h));
        int c = k >> 6, kk = k & 63;
        uint32_t off = swz(n * 128 + kk * 2);
        unsigned char* base = g_WB + 32768 + widx * 65536;
        *(__nv_bfloat16*)(base + c * 16384 + off)         = h;
        *(__nv_bfloat16*)(base + 32768 + c * 16384 + off) = l;
    }
}

// ---------------------------------------------------------------------------
// Generic tensor GEMM: OUT[128-tile x 128] = epi( A' @ W ),  K=128, bf16x3.
// mode 0: A=node_feat W=W1t  out=g_P   epi: +bias(b1)
// mode 1: A=node_feat W=W3t  out=g_P3  epi: +bias(b3)
// mode 2: A=g_sums*inv(cnt) W=W23 out=g_P(T) epi: relu(P3 + acc + flag*b23)
// mode 3: A=g_P(T) W=W4 out=param epi: +bias(b4)
// SMEM: [0,32K) Whi(c0,c1) | [32K,64K) Wlo | [64K,96K) Ahi | [96K,128K) Alo
//       [128K] bias[128]f
#define NW_HI 0
#define NW_LO 32768
#define NA_HI 65536
#define NA_LO 98304
#define NS_BIAS 131072
#define GEMM_SMEM (131072 + 512)

__global__ __launch_bounds__(256, 1)
void gemm128_kernel(const float* __restrict__ A, const float* __restrict__ bias,
                    float* __restrict__ out, int rows, int mode, int widx) {
    extern __shared__ char smc[];
    const uint32_t smb = smem_u32(smc);
    const int tid = threadIdx.x;
    const int wid = tid >> 5;
    const int lid = tid & 31;
    float* s_bias = (float*)(smc + NS_BIAS);

    const float* Ain = (mode == 2) ? g_sums : (mode == 3) ? g_P : A;
    float* O = (mode == 0 || mode == 2) ? g_P : (mode == 1) ? g_P3 : out;

    {   // stage weights (64 KB pre-swizzled image)
        const float4* src = (const float4*)(g_WB + 32768 + widx * 65536);
        float4* dst = (float4*)smc;
        #pragma unroll
        for (int i = 0; i < 16; i++) dst[tid + 256 * i] = src[tid + 256 * i];
    }
    if (tid < 128) s_bias[tid] = (mode == 2) ? g_b23[tid] : bias[tid];

    const int m0 = blockIdx.x * 128;
    {   // stage A tile: fp32 -> bf16 hi/lo, swizzled, 2 threads/row
        const int r = tid >> 1;
        const int chunk = tid & 1;           // K-chunk 0 or 1
        const int gr = m0 + r;
        const bool valid = gr < rows;
        float s = 1.f;
        if (mode == 2 && valid) s = 1.f / fmaxf(g_cnt[gr], 1.f);
        const float* src = Ain + (size_t)gr * 128 + chunk * 64;
        #pragma unroll
        for (int j = 0; j < 16; j++) {
            float4 v = valid ? *(const float4*)(src + j * 4)
                             : make_float4(0.f, 0.f, 0.f, 0.f);
            v.x *= s; v.y *= s; v.z *= s; v.w *= s;
            uint32_t hi0, lo0, hi1, lo1;
            split2(v.x, v.y, hi0, lo0);
            split2(v.z, v.w, hi1, lo1);
            uint32_t off = swz(r * 128 + j * 8);
            *(uint2*)(smc + NA_HI + chunk * 16384 + off) = make_uint2(hi0, hi1);
            *(uint2*)(smc + NA_LO + chunk * 16384 + off) = make_uint2(lo0, lo1);
        }
    }
    __syncthreads();

    // fragment geometry
    const int wr0 = wid * 16;
    const int qr = lid >> 2, qc = (lid & 3) * 2;
    const int r0 = wr0 + qr, r1 = r0 + 8;
    const int am = lid >> 3;
    const int arow = wr0 + ((am & 1) << 3) + (lid & 7);
    const int akof = (am >> 1) << 4;
    const int brow = lid & 7;
    const int bkof = ((lid >> 3) & 1) << 4;

    float acc[16][4];
    #pragma unroll
    for (int nt = 0; nt < 16; nt++)
        #pragma unroll
        for (int v = 0; v < 4; v++) acc[nt][v] = 0.f;

    #pragma unroll
    for (int kt = 0; kt < 8; kt++) {
        const int chunk = (kt >> 2) * 16384;
        const int kb = (kt & 3) * 32;
        uint32_t ahi[4], alo[4];
        ldsm_x4(ahi, smb + NA_HI + chunk + swz(arow * 128 + kb + akof));
        ldsm_x4(alo, smb + NA_LO + chunk + swz(arow * 128 + kb + akof));
        #pragma unroll
        for (int nt = 0; nt < 16; nt++) {
            uint32_t bo = swz((nt * 8 + brow) * 128 + kb + bkof);
            uint32_t bhi[2], blo[2];
            ldsm_x2(bhi, smb + NW_HI + chunk + bo);
            ldsm_x2(blo, smb + NW_LO + chunk + bo);
            mma_bf16(acc[nt], ahi, bhi);
            mma_bf16(acc[nt], ahi, blo);
            mma_bf16(acc[nt], alo, bhi);
        }
    }

    const int gr0 = m0 + r0, gr1 = m0 + r1;
    if (mode == 2) {
        const float f0 = (gr0 < rows && g_cnt[gr0] > 0.f) ? 1.f : 0.f;
        const float f1 = (gr1 < rows && g_cnt[gr1] > 0.f) ? 1.f : 0.f;
        #pragma unroll
        for (int nt = 0; nt < 16; nt++) {
            const int c = nt * 8 + qc;
            if (gr0 < rows) {
                float2 p = *(const float2*)(g_P3 + (size_t)gr0 * 128 + c);
                float2 o = make_float2(
                    fmaxf(p.x + acc[nt][0] + f0 * s_bias[c], 0.f),
                    fmaxf(p.y + acc[nt][1] + f0 * s_bias[c + 1], 0.f));
                *(float2*)(O + (size_t)gr0 * 128 + c) = o;
            }
            if (gr1 < rows) {
                float2 p = *(const float2*)(g_P3 + (size_t)gr1 * 128 + c);
                float2 o = make_float2(
                    fmaxf(p.x + acc[nt][2] + f1 * s_bias[c], 0.f),
                    fmaxf(p.y + acc[nt][3] + f1 * s_bias[c + 1], 0.f));
                *(float2*)(O + (size_t)gr1 * 128 + c) = o;
            }
        }
    } else {
        #pragma unroll
        for (int nt = 0; nt < 16; nt++) {
            const int c = nt * 8 + qc;
            if (gr0 < rows)
                *(float2*)(O + (size_t)gr0 * 128 + c) = make_float2(
                    acc[nt][0] + s_bias[c], acc[nt][1] + s_bias[c + 1]);
            if (gr1 < rows)
                *(float2*)(O + (size_t)gr1 * 128 + c) = make_float2(
                    acc[nt][2] + s_bias[c], acc[nt][3] + s_bias[c + 1]);
        }
    }
}

// ---------------------------------------------------------------------------
// Edge kernel: GEMM1 only (bf16x3), then scatter relu(D1 + P[col]) -> g_sums.
// SMEM: [0,16K) B1hi | 16K B1lo | 32K AHI | 48K ALO | 64K s_row,s_col
#define SM_B1HI 0
#define SM_B1LO 16384
#define SM_AHI  32768
#define SM_ALO  49152
#define SM_IDX  65536
#define EDGE_SMEM_BYTES (65536 + 1024)

__global__ __launch_bounds__(256, 2)
void edge_kernel_mma(const float* __restrict__ ea, const int* __restrict__ eidx,
                     int E, int ntiles) {
    extern __shared__ char smc[];
    const uint32_t smb = smem_u32(smc);
    const int tid = threadIdx.x;
    const int wid = tid >> 5;
    const int lid = tid & 31;

    int* s_row = (int*)(smc + SM_IDX);
    int* s_col = s_row + 128;

    {   // weights once (32 KB)
        const float4* src = (const float4*)g_WB;
        float4* dst = (float4*)smc;
        for (int i = tid; i < 2048; i += 256) dst[i] = src[i];
    }

    const int wr0 = wid * 16;
    const int qr = lid >> 2, qc = (lid & 3) * 2;
    const int r0 = wr0 + qr, r1 = r0 + 8;
    const int am = lid >> 3;
    const int arow = wr0 + ((am & 1) << 3) + (lid & 7);
    const int akof = (am >> 1) << 4;
    const int brow = lid & 7;
    const int bkof = ((lid >> 3) & 1) << 4;

    for (int tile = blockIdx.x; tile < ntiles; tile += gridDim.x) {
        const int e0 = tile * 128;

        if (tid < 128) {
            int e = e0 + tid;
            s_row[tid] = (e < E) ? eidx[e] : 0;
        } else {
            int t = tid - 128, e = e0 + t;
            s_col[t] = (e < E) ? eidx[(size_t)E + e] : 0;
        }
        {   // stage edge_attr -> bf16 hi/lo (2 threads/row)
            const int r = tid >> 1;
            const int cb = (tid & 1) * 32;
            const int e = e0 + r;
            const float* src = ea + (size_t)e * EF + cb;
            #pragma unroll
            for (int j = 0; j < 8; j++) {
                float4 v = (e < E) ? *(const float4*)(src + j * 4)
                                   : make_float4(0.f, 0.f, 0.f, 0.f);
                uint32_t hi0, lo0, hi1, lo1;
                split2(v.x, v.y, hi0, lo0);
                split2(v.z, v.w, hi1, lo1);
                uint32_t off = swz(r * 128 + (cb + j * 4) * 2);
                *(uint2*)(smc + SM_AHI + off) = make_uint2(hi0, hi1);
                *(uint2*)(smc + SM_ALO + off) = make_uint2(lo0, lo1);
            }
        }
        __syncthreads();

        float acc[16][4];
        #pragma unroll
        for (int nt = 0; nt < 16; nt++)
            #pragma unroll
            for (int v = 0; v < 4; v++) acc[nt][v] = 0.f;

        #pragma unroll
        for (int kt = 0; kt < 4; kt++) {
            const int kb = kt * 32;
            uint32_t ahi[4], alo[4];
            ldsm_x4(ahi, smb + SM_AHI + swz(arow * 128 + kb + akof));
            ldsm_x4(alo, smb + SM_ALO + swz(arow * 128 + kb + akof));
            #pragma unroll
            for (int nt = 0; nt < 16; nt++) {
                uint32_t bo = swz((nt * 8 + brow) * 128 + kb + bkof);
                uint32_t bhi[2], blo[2];
                ldsm_x2(bhi, smb + SM_B1HI + bo);
                ldsm_x2(blo, smb + SM_B1LO + bo);
                mma_bf16(acc[nt], ahi, bhi);
                mma_bf16(acc[nt], ahi, blo);
                mma_bf16(acc[nt], alo, bhi);
            }
        }

        // epilogue: h = relu(D1 + P[col]); scatter-add to g_sums[row]
        {
            const bool v0 = (e0 + r0 < E), v1 = (e0 + r1 < E);
            const float* P0 = g_P + (size_t)s_col[r0] * 128;
            const float* P1 = g_P + (size_t)s_col[r1] * 128;
            float* S0 = g_sums + (size_t)s_row[r0] * 128;
            float* S1 = g_sums + (size_t)s_row[r1] * 128;
            #pragma unroll
            for (int nt = 0; nt < 16; nt++) {
                const int c = nt * 8 + qc;
                if (v0) {
                    float2 p = *(const float2*)(P0 + c);
                    atomicAdd((float2*)(S0 + c),
                              make_float2(fmaxf(acc[nt][0] + p.x, 0.f),
                                          fmaxf(acc[nt][1] + p.y, 0.f)));
                }
                if (v1) {
                    float2 p = *(const float2*)(P1 + c);
                    atomicAdd((float2*)(S1 + c),
                              make_float2(fmaxf(acc[nt][2] + p.x, 0.f),
                                          fmaxf(acc[nt][3] + p.y, 0.f)));
                }
            }
        }
        if (tid < 128 && e0 + tid < E) atomicAdd(&g_cnt[s_row[tid]], 1.0f);
        __syncthreads();   // protect A staging + idx before next tile
    }
}

// ---------------------------------------------------------------------------
extern "C" void kernel_launch(void* const* d_in, const int* in_sizes, int n_in,
                              void* d_out, int out_size) {
    const float* node_feat = (const float*)d_in[0];
    const int*   eidx      = (const int*)d_in[1];   // int32 (JAX x64 disabled)
    const float* ea        = (const float*)d_in[2];
    const float* W1 = (const float*)d_in[3];
    const float* b1 = (const float*)d_in[4];
    const float* W2 = (const float*)d_in[5];
    const float* b2 = (const float*)d_in[6];
    const float* W3 = (const float*)d_in[7];
    const float* b3 = (const float*)d_in[8];
    const float* W4 = (const float*)d_in[9];
    const float* b4 = (const float*)d_in[10];
    float* out = (float*)d_out;

    const int E = in_sizes[1] / 2;
    const int NBN = (N_NODES + 127) / 128;   // 391
    const int NBE = (E + 127) / 128;         // 12500

    cudaFuncSetAttribute(gemm128_kernel,
                         cudaFuncAttributeMaxDynamicSharedMemorySize, GEMM_SMEM);
    cudaFuncSetAttribute(edge_kernel_mma,
                         cudaFuncAttributeMaxDynamicSharedMemorySize, EDGE_SMEM_BYTES);

    zero_kernel<<<1024, 256>>>();
    prep1_kernel<<<129, 128>>>(W2, W3, b2);
    prep2_kernel<<<64, 256>>>(W1, W3, W4);
    // P = nf@W1_top + b1 ; P3 = nf@W3_top + b3
    gemm128_kernel<<<NBN, 256, GEMM_SMEM>>>(node_feat, b1, nullptr, N_NODES, 0, 0);
    gemm128_kernel<<<NBN, 256, GEMM_SMEM>>>(node_feat, b3, nullptr, N_NODES, 1, 1);
    // edge: scatter relu(P[col] + ea@W1_bot)
    edge_kernel_mma<<<296, 256, EDGE_SMEM_BYTES>>>(ea, eidx, E, NBE);
    // T = relu(P3 + mean_h@W23 + flag*b23) ; out = T@W4 + b4
    gemm128_kernel<<<NBN, 256, GEMM_SMEM>>>(nullptr, nullptr, nullptr, N_NODES, 2, 2);
    gemm128_kernel<<<NBN, 256, GEMM_SMEM>>>(nullptr, b4, out, N_NODES, 3, 3);
}

// round 6
// speedup vs baseline: 3.4163x; 1.2170x over previous
#include <cuda_runtime.h>
#include <cuda_bf16.h>
#include <cstdint>

#define N_NODES 50000
#define HID 128
#define EF 64

// ---------------------------------------------------------------------------
// Scratch (device globals — allocation-free per harness rules)
__device__ float g_P   [(size_t)N_NODES * HID];   // node_feat@W1_top+b1
__device__ float g_P3  [(size_t)N_NODES * HID];   // node_feat@W3_top+b3
__device__ float g_sums[(size_t)N_NODES * HID];   // scatter-add of relu-h
__device__ float g_cnt [N_NODES];
__device__ float g_W23 [128 * 128];               // W2 @ W3_bot (fp32)
__device__ float g_b23 [128];                     // b2 @ W3_bot
// bf16 hi/lo weight images, [N][K] K-major 128B rows, SW128-swizzled.
// [0,16K) B1hi | [16K,32K) B1lo | then 4 node weights x 64KB each:
//   base+0 hi c0 | +16K hi c1 | +32K lo c0 | +48K lo c1
// widx: 0=W1_top 1=W3_top 2=W23 3=W4
__device__ __align__(16) unsigned char g_WB[32768 + 4 * 65536];

__device__ __forceinline__ uint32_t smem_u32(const void* p) {
    uint32_t a;
    asm("{ .reg .u64 t; cvta.to.shared.u64 t, %1; cvt.u32.u64 %0, t; }"
        : "=r"(a) : "l"(p));
    return a;
}
__device__ __forceinline__ uint32_t swz(uint32_t b) { return b ^ ((b >> 3) & 0x70); }

__device__ __forceinline__ void ldsm_x4(uint32_t* r, uint32_t addr) {
    asm volatile("ldmatrix.sync.aligned.m8n8.x4.shared.b16 {%0,%1,%2,%3}, [%4];"
                 : "=r"(r[0]), "=r"(r[1]), "=r"(r[2]), "=r"(r[3]) : "r"(addr));
}
__device__ __forceinline__ void ldsm_x2(uint32_t* r, uint32_t addr) {
    asm volatile("ldmatrix.sync.aligned.m8n8.x2.shared.b16 {%0,%1}, [%2];"
                 : "=r"(r[0]), "=r"(r[1]) : "r"(addr));
}
__device__ __forceinline__ void mma_bf16(float* d, const uint32_t* a, const uint32_t* b) {
    asm volatile("mma.sync.aligned.m16n8k16.row.col.f32.bf16.bf16.f32 "
                 "{%0,%1,%2,%3}, {%4,%5,%6,%7}, {%8,%9}, {%0,%1,%2,%3};"
                 : "+f"(d[0]), "+f"(d[1]), "+f"(d[2]), "+f"(d[3])
                 : "r"(a[0]), "r"(a[1]), "r"(a[2]), "r"(a[3]), "r"(b[0]), "r"(b[1]));
}
__device__ __forceinline__ uint32_t pack_bf16x2(float x, float y) {
    __nv_bfloat162 p = {__float2bfloat16(x), __float2bfloat16(y)};
    return *(uint32_t*)&p;
}
__device__ __forceinline__ void split2(float x, float y, uint32_t& hi, uint32_t& lo) {
    __nv_bfloat16 hx = __float2bfloat16(x), hy = __float2bfloat16(y);
    __nv_bfloat162 ph = {hx, hy};
    hi = *(uint32_t*)&ph;
    lo = pack_bf16x2(x - __bfloat162float(hx), y - __bfloat162float(hy));
}

// Shared K=128 bf16x3 GEMM core. A image at aoff, W image at woff; both are
// [hi c0 16K | hi c1 16K | lo c0 16K | lo c1 16K].
__device__ __forceinline__ void gemm128_core(
    uint32_t smb, uint32_t aoff, uint32_t woff,
    int arow, int akof, int brow, int bkof, float acc[16][4]) {
    #pragma unroll
    for (int kt = 0; kt < 8; kt++) {
        const int chunk = (kt >> 2) * 16384;
        const int kb = (kt & 3) * 32;
        uint32_t ahi[4], alo[4];
        ldsm_x4(ahi, smb + aoff + chunk + swz(arow * 128 + kb + akof));
        ldsm_x4(alo, smb + aoff + 32768 + chunk + swz(arow * 128 + kb + akof));
        #pragma unroll
        for (int nt = 0; nt < 16; nt++) {
            uint32_t bo = swz((nt * 8 + brow) * 128 + kb + bkof);
            uint32_t bhi[2], blo[2];
            ldsm_x2(bhi, smb + woff + chunk + bo);
            ldsm_x2(blo, smb + woff + 32768 + chunk + bo);
            mma_bf16(acc[nt], ahi, bhi);
            mma_bf16(acc[nt], ahi, blo);
            mma_bf16(acc[nt], alo, bhi);
        }
    }
}

// ---------------------------------------------------------------------------
__global__ void zero_kernel() {
    const size_t total4 = (size_t)N_NODES * HID / 4;
    float4* s = (float4*)g_sums;
    const float4 z = make_float4(0.f, 0.f, 0.f, 0.f);
    for (size_t i = (size_t)blockIdx.x * blockDim.x + threadIdx.x; i < total4;
         i += (size_t)gridDim.x * blockDim.x)
        s[i] = z;
    for (int i = blockIdx.x * blockDim.x + threadIdx.x; i < N_NODES;
         i += gridDim.x * blockDim.x)
        g_cnt[i] = 0.f;
}

// ---------------------------------------------------------------------------
// W23 = W2 @ W3[128:256], b23 = b2 @ W3[128:256]
__global__ void prep1_kernel(const float* __restrict__ W2,
                             const float* __restrict__ W3,
                             const float* __restrict__ b2) {
    __shared__ float srow[128];
    const int r = blockIdx.x;     // 0..128 (128 == b23 row)
    const int c = threadIdx.x;
    srow[c] = (r < 128) ? W2[r * 128 + c] : b2[c];
    __syncthreads();
    float acc = 0.f;
    #pragma unroll 4
    for (int k = 0; k < 128; k++)
        acc += srow[k] * W3[(128 + k) * 128 + c];
    if (r < 128) g_W23[r * 128 + c] = acc;
    else         g_b23[c] = acc;
}

// ---------------------------------------------------------------------------
__global__ void prep2_kernel(const float* __restrict__ W1,
                             const float* __restrict__ W3,
                             const float* __restrict__ W4) {
    const int tid = blockIdx.x * blockDim.x + threadIdx.x;
    const int nth = gridDim.x * blockDim.x;
    for (int i = tid; i < 128 * 64; i += nth) {       // edge B1 = W1 rows 128..191
        int n = i >> 6, k = i & 63;
        float v = W1[(128 + k) * 128 + n];
        __nv_bfloat16 h = __float2bfloat16(v);
        __nv_bfloat16 l = __float2bfloat16(v - __bfloat162float(h));
        uint32_t off = swz(n * 128 + k * 2);
        *(__nv_bfloat16*)(g_WB + off)         = h;
        *(__nv_bfloat16*)(g_WB + 16384 + off) = l;
    }
    for (int i = tid; i < 4 * 128 * 128; i += nth) {  // node weights
        int widx = i >> 14, j = i & 16383;
        int n = j >> 7, k = j & 127;
        float v;
        if      (widx == 0) v = W1[k * 128 + n];
        else if (widx == 1) v = W3[k * 128 + n];
        else if (widx == 2) v = g_W23[k * 128 + n];
        else                v = W4[k * 128 + n];
        __nv_bfloat16 h = __float2bfloat16(v);
        __nv_bfloat16 l = __float2bfloat16(v - __bfloat162float(h));
        int c = k >> 6, kk = k & 63;
        uint32_t off = swz(n * 128 + kk * 2);
        unsigned char* base = g_WB + 32768 + widx * 65536;
        *(__nv_bfloat16*)(base + c * 16384 + off)         = h;
        *(__nv_bfloat16*)(base + 32768 + c * 16384 + off) = l;
    }
}

// ---------------------------------------------------------------------------
// pre_both: stage node_feat once; P = nf@W1t + b1; P3 = nf@W3t + b3.
// SMEM: [0,64K) W image | [64K,128K) A image | 128K: b1[128], b3[128]
#define PB_W 0
#define PB_A 65536
#define PB_BIAS 131072
#define PB_SMEM (131072 + 1024)

__global__ __launch_bounds__(256, 1)
void pre_both_kernel(const float* __restrict__ A, const float* __restrict__ b1,
                     const float* __restrict__ b3) {
    extern __shared__ char smc[];
    const uint32_t smb = smem_u32(smc);
    const int tid = threadIdx.x;
    const int wid = tid >> 5;
    const int lid = tid & 31;
    float* s_b1 = (float*)(smc + PB_BIAS);
    float* s_b3 = s_b1 + 128;

    {   // W1_top image
        const float4* src = (const float4*)(g_WB + 32768);
        float4* dst = (float4*)smc;
        #pragma unroll
        for (int i = 0; i < 16; i++) dst[tid + 256 * i] = src[tid + 256 * i];
    }
    if (tid < 128) { s_b1[tid] = b1[tid]; s_b3[tid] = b3[tid]; }

    const int m0 = blockIdx.x * 128;
    {   // stage A (node_feat) -> bf16 hi/lo
        const int r = tid >> 1;
        const int chunk = tid & 1;
        const int gr = m0 + r;
        const bool valid = gr < N_NODES;
        const float* src = A + (size_t)gr * 128 + chunk * 64;
        #pragma unroll
        for (int j = 0; j < 16; j++) {
            float4 v = valid ? *(const float4*)(src + j * 4)
                             : make_float4(0.f, 0.f, 0.f, 0.f);
            uint32_t hi0, lo0, hi1, lo1;
            split2(v.x, v.y, hi0, lo0);
            split2(v.z, v.w, hi1, lo1);
            uint32_t off = swz(r * 128 + j * 8);
            *(uint2*)(smc + PB_A + chunk * 16384 + off) = make_uint2(hi0, hi1);
            *(uint2*)(smc + PB_A + 32768 + chunk * 16384 + off) = make_uint2(lo0, lo1);
        }
    }
    __syncthreads();

    const int wr0 = wid * 16;
    const int qr = lid >> 2, qc = (lid & 3) * 2;
    const int r0 = wr0 + qr, r1 = r0 + 8;
    const int am = lid >> 3;
    const int arow = wr0 + ((am & 1) << 3) + (lid & 7);
    const int akof = (am >> 1) << 4;
    const int brow = lid & 7;
    const int bkof = ((lid >> 3) & 1) << 4;
    const int gr0 = m0 + r0, gr1 = m0 + r1;

    float acc[16][4];
    #pragma unroll
    for (int nt = 0; nt < 16; nt++)
        #pragma unroll
        for (int v = 0; v < 4; v++) acc[nt][v] = 0.f;
    gemm128_core(smb, PB_A, PB_W, arow, akof, brow, bkof, acc);
    #pragma unroll
    for (int nt = 0; nt < 16; nt++) {
        const int c = nt * 8 + qc;
        if (gr0 < N_NODES)
            *(float2*)(g_P + (size_t)gr0 * 128 + c) = make_float2(
                acc[nt][0] + s_b1[c], acc[nt][1] + s_b1[c + 1]);
        if (gr1 < N_NODES)
            *(float2*)(g_P + (size_t)gr1 * 128 + c) = make_float2(
                acc[nt][2] + s_b1[c], acc[nt][3] + s_b1[c + 1]);
    }
    __syncthreads();
    {   // swap to W3_top image
        const float4* src = (const float4*)(g_WB + 32768 + 65536);
        float4* dst = (float4*)smc;
        #pragma unroll
        for (int i = 0; i < 16; i++) dst[tid + 256 * i] = src[tid + 256 * i];
    }
    __syncthreads();
    #pragma unroll
    for (int nt = 0; nt < 16; nt++)
        #pragma unroll
        for (int v = 0; v < 4; v++) acc[nt][v] = 0.f;
    gemm128_core(smb, PB_A, PB_W, arow, akof, brow, bkof, acc);
    #pragma unroll
    for (int nt = 0; nt < 16; nt++) {
        const int c = nt * 8 + qc;
        if (gr0 < N_NODES)
            *(float2*)(g_P3 + (size_t)gr0 * 128 + c) = make_float2(
                acc[nt][0] + s_b3[c], acc[nt][1] + s_b3[c + 1]);
        if (gr1 < N_NODES)
            *(float2*)(g_P3 + (size_t)gr1 * 128 + c) = make_float2(
                acc[nt][2] + s_b3[c], acc[nt][3] + s_b3[c + 1]);
    }
}

// ---------------------------------------------------------------------------
// node_fused: mean = sums/max(cnt,1); T = relu(P3 + mean@W23 + flag*b23);
// out = T@W4 + b4. T restaged bf16 hi/lo in the A region between GEMMs.
__global__ __launch_bounds__(256, 1)
void node_fused_kernel(const float* __restrict__ b4, float* __restrict__ out) {
    extern __shared__ char smc[];
    const uint32_t smb = smem_u32(smc);
    const int tid = threadIdx.x;
    const int wid = tid >> 5;
    const int lid = tid & 31;
    float* s_b23 = (float*)(smc + PB_BIAS);
    float* s_b4  = s_b23 + 128;

    {   // W23 image
        const float4* src = (const float4*)(g_WB + 32768 + 2 * 65536);
        float4* dst = (float4*)smc;
        #pragma unroll
        for (int i = 0; i < 16; i++) dst[tid + 256 * i] = src[tid + 256 * i];
    }
    if (tid < 128) { s_b23[tid] = g_b23[tid]; s_b4[tid] = b4[tid]; }

    const int m0 = blockIdx.x * 128;
    {   // stage mean -> bf16 hi/lo
        const int r = tid >> 1;
        const int chunk = tid & 1;
        const int gr = m0 + r;
        const bool valid = gr < N_NODES;
        float s = valid ? 1.f / fmaxf(g_cnt[gr], 1.f) : 0.f;
        const float* src = g_sums + (size_t)gr * 128 + chunk * 64;
        #pragma unroll
        for (int j = 0; j < 16; j++) {
            float4 v = valid ? *(const float4*)(src + j * 4)
                             : make_float4(0.f, 0.f, 0.f, 0.f);
            v.x *= s; v.y *= s; v.z *= s; v.w *= s;
            uint32_t hi0, lo0, hi1, lo1;
            split2(v.x, v.y, hi0, lo0);
            split2(v.z, v.w, hi1, lo1);
            uint32_t off = swz(r * 128 + j * 8);
            *(uint2*)(smc + PB_A + chunk * 16384 + off) = make_uint2(hi0, hi1);
            *(uint2*)(smc + PB_A + 32768 + chunk * 16384 + off) = make_uint2(lo0, lo1);
        }
    }
    __syncthreads();

    const int wr0 = wid * 16;
    const int qr = lid >> 2, qc = (lid & 3) * 2;
    const int r0 = wr0 + qr, r1 = r0 + 8;
    const int am = lid >> 3;
    const int arow = wr0 + ((am & 1) << 3) + (lid & 7);
    const int akof = (am >> 1) << 4;
    const int brow = lid & 7;
    const int bkof = ((lid >> 3) & 1) << 4;
    const int gr0 = m0 + r0, gr1 = m0 + r1;

    float acc[16][4];
    #pragma unroll
    for (int nt = 0; nt < 16; nt++)
        #pragma unroll
        for (int v = 0; v < 4; v++) acc[nt][v] = 0.f;
    gemm128_core(smb, PB_A, PB_W, arow, akof, brow, bkof, acc);

    // T = relu(P3 + acc + flag*b23) -> restage into A region (own warp strip)
    {
        const float f0 = (gr0 < N_NODES && g_cnt[gr0] > 0.f) ? 1.f : 0.f;
        const float f1 = (gr1 < N_NODES && g_cnt[gr1] > 0.f) ? 1.f : 0.f;
        #pragma unroll
        for (int nt = 0; nt < 16; nt++) {
            const int c = nt * 8 + qc;
            float t00 = 0.f, t01 = 0.f, t10 = 0.f, t11 = 0.f;
            if (gr0 < N_NODES) {
                float2 p = *(const float2*)(g_P3 + (size_t)gr0 * 128 + c);
                t00 = fmaxf(p.x + acc[nt][0] + f0 * s_b23[c], 0.f);
                t01 = fmaxf(p.y + acc[nt][1] + f0 * s_b23[c + 1], 0.f);
            }
            if (gr1 < N_NODES) {
                float2 p = *(const float2*)(g_P3 + (size_t)gr1 * 128 + c);
                t10 = fmaxf(p.x + acc[nt][2] + f1 * s_b23[c], 0.f);
                t11 = fmaxf(p.y + acc[nt][3] + f1 * s_b23[c + 1], 0.f);
            }
            uint32_t hi0, lo0, hi1, lo1;
            split2(t00, t01, hi0, lo0);
            split2(t10, t11, hi1, lo1);
            const int chunk = (c >> 6) * 16384;
            const int kk2 = (c & 63) * 2;
            *(uint32_t*)(smc + PB_A + chunk + swz(r0 * 128 + kk2)) = hi0;
            *(uint32_t*)(smc + PB_A + chunk + swz(r1 * 128 + kk2)) = hi1;
            *(uint32_t*)(smc + PB_A + 32768 + chunk + swz(r0 * 128 + kk2)) = lo0;
            *(uint32_t*)(smc + PB_A + 32768 + chunk + swz(r1 * 128 + kk2)) = lo1;
        }
    }
    __syncthreads();
    {   // swap to W4 image
        const float4* src = (const float4*)(g_WB + 32768 + 3 * 65536);
        float4* dst = (float4*)smc;
        #pragma unroll
        for (int i = 0; i < 16; i++) dst[tid + 256 * i] = src[tid + 256 * i];
    }
    __syncthreads();
    #pragma unroll
    for (int nt = 0; nt < 16; nt++)
        #pragma unroll
        for (int v = 0; v < 4; v++) acc[nt][v] = 0.f;
    gemm128_core(smb, PB_A, PB_W, arow, akof, brow, bkof, acc);
    #pragma unroll
    for (int nt = 0; nt < 16; nt++) {
        const int c = nt * 8 + qc;
        if (gr0 < N_NODES)
            *(float2*)(out + (size_t)gr0 * 128 + c) = make_float2(
                acc[nt][0] + s_b4[c], acc[nt][1] + s_b4[c + 1]);
        if (gr1 < N_NODES)
            *(float2*)(out + (size_t)gr1 * 128 + c) = make_float2(
                acc[nt][2] + s_b4[c], acc[nt][3] + s_b4[c + 1]);
    }
}

// ---------------------------------------------------------------------------
// Edge kernel: D1 = ea@W1_bot (bf16x3, K=64); scatter relu(D1 + P[col]) via
// shuffle-vectorized float4 gathers/REDs.
#define SM_B1HI 0
#define SM_B1LO 16384
#define SM_AHI  32768
#define SM_ALO  49152
#define SM_IDX  65536
#define EDGE_SMEM_BYTES (65536 + 1024)

__global__ __launch_bounds__(256, 2)
void edge_kernel_mma(const float* __restrict__ ea, const int* __restrict__ eidx,
                     int E, int ntiles) {
    extern __shared__ char smc[];
    const uint32_t smb = smem_u32(smc);
    const int tid = threadIdx.x;
    const int wid = tid >> 5;
    const int lid = tid & 31;

    int* s_row = (int*)(smc + SM_IDX);
    int* s_col = s_row + 128;

    {   // weights once (32 KB)
        const float4* src = (const float4*)g_WB;
        float4* dst = (float4*)smc;
        for (int i = tid; i < 2048; i += 256) dst[i] = src[i];
    }

    const int wr0 = wid * 16;
    const int qr = lid >> 2;
    const int r0 = wr0 + qr, r1 = r0 + 8;
    const int am = lid >> 3;
    const int arow = wr0 + ((am & 1) << 3) + (lid & 7);
    const int akof = (am >> 1) << 4;
    const int brow = lid & 7;
    const int bkof = ((lid >> 3) & 1) << 4;
    // epilogue shuffle geometry: even lanes own row r0, odd lanes row r1;
    // column quad base = (lid&2 ? 4 : 0) within each nt's 8 columns.
    const int cboff = (lid & 2) ? 4 : 0;
    const bool evenlane = ((lid & 1) == 0);
    const int myrow = evenlane ? r0 : r1;

    for (int tile = blockIdx.x; tile < ntiles; tile += gridDim.x) {
        const int e0 = tile * 128;

        if (tid < 128) {
            int e = e0 + tid;
            s_row[tid] = (e < E) ? eidx[e] : 0;
        } else {
            int t = tid - 128, e = e0 + t;
            s_col[t] = (e < E) ? eidx[(size_t)E + e] : 0;
        }
        {   // stage edge_attr -> bf16 hi/lo (2 threads/row)
            const int r = tid >> 1;
            const int cb = (tid & 1) * 32;
            const int e = e0 + r;
            const float* src = ea + (size_t)e * EF + cb;
            #pragma unroll
            for (int j = 0; j < 8; j++) {
                float4 v = (e < E) ? *(const float4*)(src + j * 4)
                                   : make_float4(0.f, 0.f, 0.f, 0.f);
                uint32_t hi0, lo0, hi1, lo1;
                split2(v.x, v.y, hi0, lo0);
                split2(v.z, v.w, hi1, lo1);
                uint32_t off = swz(r * 128 + (cb + j * 4) * 2);
                *(uint2*)(smc + SM_AHI + off) = make_uint2(hi0, hi1);
                *(uint2*)(smc + SM_ALO + off) = make_uint2(lo0, lo1);
            }
        }
        __syncthreads();

        float acc[16][4];
        #pragma unroll
        for (int nt = 0; nt < 16; nt++)
            #pragma unroll
            for (int v = 0; v < 4; v++) acc[nt][v] = 0.f;

        #pragma unroll
        for (int kt = 0; kt < 4; kt++) {
            const int kb = kt * 32;
            uint32_t ahi[4], alo[4];
            ldsm_x4(ahi, smb + SM_AHI + swz(arow * 128 + kb + akof));
            ldsm_x4(alo, smb + SM_ALO + swz(arow * 128 + kb + akof));
            #pragma unroll
            for (int nt = 0; nt < 16; nt++) {
                uint32_t bo = swz((nt * 8 + brow) * 128 + kb + bkof);
                uint32_t bhi[2], blo[2];
                ldsm_x2(bhi, smb + SM_B1HI + bo);
                ldsm_x2(blo, smb + SM_B1LO + bo);
                mma_bf16(acc[nt], ahi, bhi);
                mma_bf16(acc[nt], ahi, blo);
                mma_bf16(acc[nt], alo, bhi);
            }
        }

        // epilogue: shuffle to float4 quads; h = relu(D1 + P[col]); RED.F32X4
        {
            const bool valid = (e0 + myrow < E);
            const float* Pn = g_P + (size_t)s_col[myrow] * 128 + cboff;
            float* Sn = g_sums + (size_t)s_row[myrow] * 128 + cboff;
            #pragma unroll
            for (int nt = 0; nt < 16; nt++) {
                float sA = evenlane ? acc[nt][2] : acc[nt][0];
                float sB = evenlane ? acc[nt][3] : acc[nt][1];
                float rA = __shfl_xor_sync(0xFFFFFFFFu, sA, 1);
                float rB = __shfl_xor_sync(0xFFFFFFFFu, sB, 1);
                float4 v = evenlane
                    ? make_float4(acc[nt][0], acc[nt][1], rA, rB)
                    : make_float4(rA, rB, acc[nt][2], acc[nt][3]);
                if (valid) {
                    float4 p = *(const float4*)(Pn + nt * 8);
                    v.x = fmaxf(v.x + p.x, 0.f);
                    v.y = fmaxf(v.y + p.y, 0.f);
                    v.z = fmaxf(v.z + p.z, 0.f);
                    v.w = fmaxf(v.w + p.w, 0.f);
                    atomicAdd((float4*)(Sn + nt * 8), v);
                }
            }
        }
        if (tid < 128 && e0 + tid < E) atomicAdd(&g_cnt[s_row[tid]], 1.0f);
        __syncthreads();   // protect A staging + idx before next tile
    }
}

// ---------------------------------------------------------------------------
extern "C" void kernel_launch(void* const* d_in, const int* in_sizes, int n_in,
                              void* d_out, int out_size) {
    const float* node_feat = (const float*)d_in[0];
    const int*   eidx      = (const int*)d_in[1];   // int32 (JAX x64 disabled)
    const float* ea        = (const float*)d_in[2];
    const float* W1 = (const float*)d_in[3];
    const float* b1 = (const float*)d_in[4];
    const float* W2 = (const float*)d_in[5];
    const float* b2 = (const float*)d_in[6];
    const float* W3 = (const float*)d_in[7];
    const float* b3 = (const float*)d_in[8];
    const float* W4 = (const float*)d_in[9];
    const float* b4 = (const float*)d_in[10];
    float* out = (float*)d_out;

    const int E = in_sizes[1] / 2;
    const int NBN = (N_NODES + 127) / 128;   // 391
    const int NBE = (E + 127) / 128;         // 12500

    cudaFuncSetAttribute(pre_both_kernel,
                         cudaFuncAttributeMaxDynamicSharedMemorySize, PB_SMEM);
    cudaFuncSetAttribute(node_fused_kernel,
                         cudaFuncAttributeMaxDynamicSharedMemorySize, PB_SMEM);
    cudaFuncSetAttribute(edge_kernel_mma,
                         cudaFuncAttributeMaxDynamicSharedMemorySize, EDGE_SMEM_BYTES);

    zero_kernel<<<1024, 256>>>();
    prep1_kernel<<<129, 128>>>(W2, W3, b2);
    prep2_kernel<<<64, 256>>>(W1, W3, W4);
    pre_both_kernel<<<NBN, 256, PB_SMEM>>>(node_feat, b1, b3);
    edge_kernel_mma<<<296, 256, EDGE_SMEM_BYTES>>>(ea, eidx, E, NBE);
    node_fused_kernel<<<NBN, 256, PB_SMEM>>>(b4, out);
}

// round 7
// speedup vs baseline: 3.4785x; 1.0182x over previous
#include <cuda_runtime.h>
#include <cuda_bf16.h>
#include <cstdint>

#define N_NODES 50000
#define HID 128
#define EF 64

// ---------------------------------------------------------------------------
// Scratch (device globals — allocation-free per harness rules)
__device__ float g_P   [(size_t)N_NODES * HID];   // node_feat@W1_top+b1
__device__ float g_P3  [(size_t)N_NODES * HID];   // node_feat@W3_top+b3
__device__ float g_sums[(size_t)N_NODES * HID];   // scatter-add of relu-h
__device__ float g_cnt [N_NODES];
__device__ float g_W23 [128 * 128];               // W2 @ W3_bot (fp32)
__device__ float g_b23 [128];                     // b2 @ W3_bot
// bf16 hi/lo weight images, [N][K] K-major 128B rows, SW128-swizzled.
// [0,16K) B1hi | [16K,32K) B1lo | then 4 node weights x 64KB each:
//   base+0 hi c0 | +16K hi c1 | +32K lo c0 | +48K lo c1
// widx: 0=W1_top 1=W3_top 2=W23 3=W4
__device__ __align__(16) unsigned char g_WB[32768 + 4 * 65536];

__device__ __forceinline__ uint32_t smem_u32(const void* p) {
    uint32_t a;
    asm("{ .reg .u64 t; cvta.to.shared.u64 t, %1; cvt.u32.u64 %0, t; }"
        : "=r"(a) : "l"(p));
    return a;
}
__device__ __forceinline__ uint32_t swz(uint32_t b) { return b ^ ((b >> 3) & 0x70); }

__device__ __forceinline__ void ldsm_x4(uint32_t* r, uint32_t addr) {
    asm volatile("ldmatrix.sync.aligned.m8n8.x4.shared.b16 {%0,%1,%2,%3}, [%4];"
                 : "=r"(r[0]), "=r"(r[1]), "=r"(r[2]), "=r"(r[3]) : "r"(addr));
}
__device__ __forceinline__ void mma_bf16(float* d, const uint32_t* a, const uint32_t* b) {
    asm volatile("mma.sync.aligned.m16n8k16.row.col.f32.bf16.bf16.f32 "
                 "{%0,%1,%2,%3}, {%4,%5,%6,%7}, {%8,%9}, {%0,%1,%2,%3};"
                 : "+f"(d[0]), "+f"(d[1]), "+f"(d[2]), "+f"(d[3])
                 : "r"(a[0]), "r"(a[1]), "r"(a[2]), "r"(a[3]), "r"(b[0]), "r"(b[1]));
}
__device__ __forceinline__ uint32_t pack_bf16x2(float x, float y) {
    __nv_bfloat162 p = {__float2bfloat16(x), __float2bfloat16(y)};
    return *(uint32_t*)&p;
}
__device__ __forceinline__ void split2(float x, float y, uint32_t& hi, uint32_t& lo) {
    __nv_bfloat16 hx = __float2bfloat16(x), hy = __float2bfloat16(y);
    __nv_bfloat162 ph = {hx, hy};
    hi = *(uint32_t*)&ph;
    lo = pack_bf16x2(x - __bfloat162float(hx), y - __bfloat162float(hy));
}
// pack 8 floats (two float4) into hi/lo uint4 (bf16x2 lanes in K order)
__device__ __forceinline__ void split8(float4 v0, float4 v1, uint4& hi, uint4& lo) {
    split2(v0.x, v0.y, hi.x, lo.x);
    split2(v0.z, v0.w, hi.y, lo.y);
    split2(v1.x, v1.y, hi.z, lo.z);
    split2(v1.z, v1.w, hi.w, lo.w);
}

// Shared K=128 bf16x3 GEMM core with x4 B-operand ldmatrix.
// A image at aoff [hi c0|hi c1 @+16K... layout: hi at aoff + chunk*16K,
// lo at aoff+32768 + chunk*16K]; W image at woff, same layout.
__device__ __forceinline__ void gemm128_core(
    uint32_t smb, uint32_t aoff, uint32_t woff, int lid,
    int arow, int akof, float acc[16][4]) {
    const int ntoff = lid >> 4;
    const int brow = lid & 7;
    const int bkof = ((lid >> 3) & 1) << 4;
    #pragma unroll
    for (int kt = 0; kt < 8; kt++) {
        const int chunk = (kt >> 2) * 16384;
        const int kb = (kt & 3) * 32;
        uint32_t ahi[4], alo[4];
        ldsm_x4(ahi, smb + aoff + chunk + swz(arow * 128 + kb + akof));
        ldsm_x4(alo, smb + aoff + 32768 + chunk + swz(arow * 128 + kb + akof));
        #pragma unroll
        for (int nt = 0; nt < 16; nt += 2) {
            uint32_t bo = swz(((nt + ntoff) * 8 + brow) * 128 + kb + bkof);
            uint32_t bh[4], bl[4];
            ldsm_x4(bh, smb + woff + chunk + bo);
            ldsm_x4(bl, smb + woff + 32768 + chunk + bo);
            mma_bf16(acc[nt],     ahi, bh);
            mma_bf16(acc[nt],     ahi, bl);
            mma_bf16(acc[nt],     alo, bh);
            mma_bf16(acc[nt + 1], ahi, bh + 2);
            mma_bf16(acc[nt + 1], ahi, bl + 2);
            mma_bf16(acc[nt + 1], alo, bh + 2);
        }
    }
}

// ---------------------------------------------------------------------------
__global__ void zero_kernel() {
    const size_t total4 = (size_t)N_NODES * HID / 4;
    float4* s = (float4*)g_sums;
    const float4 z = make_float4(0.f, 0.f, 0.f, 0.f);
    for (size_t i = (size_t)blockIdx.x * blockDim.x + threadIdx.x; i < total4;
         i += (size_t)gridDim.x * blockDim.x)
        s[i] = z;
    for (int i = blockIdx.x * blockDim.x + threadIdx.x; i < N_NODES;
         i += gridDim.x * blockDim.x)
        g_cnt[i] = 0.f;
}

// ---------------------------------------------------------------------------
// W23 = W2 @ W3[128:256], b23 = b2 @ W3[128:256]
__global__ void prep1_kernel(const float* __restrict__ W2,
                             const float* __restrict__ W3,
                             const float* __restrict__ b2) {
    __shared__ float srow[128];
    const int r = blockIdx.x;     // 0..128 (128 == b23 row)
    const int c = threadIdx.x;
    srow[c] = (r < 128) ? W2[r * 128 + c] : b2[c];
    __syncthreads();
    float acc = 0.f;
    #pragma unroll 4
    for (int k = 0; k < 128; k++)
        acc += srow[k] * W3[(128 + k) * 128 + c];
    if (r < 128) g_W23[r * 128 + c] = acc;
    else         g_b23[c] = acc;
}

// ---------------------------------------------------------------------------
__global__ void prep2_kernel(const float* __restrict__ W1,
                             const float* __restrict__ W3,
                             const float* __restrict__ W4) {
    const int tid = blockIdx.x * blockDim.x + threadIdx.x;
    const int nth = gridDim.x * blockDim.x;
    for (int i = tid; i < 128 * 64; i += nth) {       // edge B1 = W1 rows 128..191
        int n = i >> 6, k = i & 63;
        float v = W1[(128 + k) * 128 + n];
        __nv_bfloat16 h = __float2bfloat16(v);
        __nv_bfloat16 l = __float2bfloat16(v - __bfloat162float(h));
        uint32_t off = swz(n * 128 + k * 2);
        *(__nv_bfloat16*)(g_WB + off)         = h;
        *(__nv_bfloat16*)(g_WB + 16384 + off) = l;
    }
    for (int i = tid; i < 4 * 128 * 128; i += nth) {  // node weights
        int widx = i >> 14, j = i & 16383;
        int n = j >> 7, k = j & 127;
        float v;
        if      (widx == 0) v = W1[k * 128 + n];
        else if (widx == 1) v = W3[k * 128 + n];
        else if (widx == 2) v = g_W23[k * 128 + n];
        else                v = W4[k * 128 + n];
        __nv_bfloat16 h = __float2bfloat16(v);
        __nv_bfloat16 l = __float2bfloat16(v - __bfloat162float(h));
        int c = k >> 6, kk = k & 63;
        uint32_t off = swz(n * 128 + kk * 2);
        unsigned char* base = g_WB + 32768 + widx * 65536;
        *(__nv_bfloat16*)(base + c * 16384 + off)         = h;
        *(__nv_bfloat16*)(base + 32768 + c * 16384 + off) = l;
    }
}

// ---------------------------------------------------------------------------
// pre_both: stage node_feat once; P = nf@W1t + b1; P3 = nf@W3t + b3.
// SMEM: [0,64K) W image | [64K,128K) A image | 128K: b1[128], b3[128]
#define PB_W 0
#define PB_A 65536
#define PB_BIAS 131072
#define PB_SMEM (131072 + 1024)

__global__ __launch_bounds__(256, 1)
void pre_both_kernel(const float* __restrict__ A, const float* __restrict__ b1,
                     const float* __restrict__ b3) {
    extern __shared__ char smc[];
    const uint32_t smb = smem_u32(smc);
    const int tid = threadIdx.x;
    const int wid = tid >> 5;
    const int lid = tid & 31;
    float* s_b1 = (float*)(smc + PB_BIAS);
    float* s_b3 = s_b1 + 128;

    {   // W1_top image
        const float4* src = (const float4*)(g_WB + 32768);
        float4* dst = (float4*)smc;
        #pragma unroll
        for (int i = 0; i < 16; i++) dst[tid + 256 * i] = src[tid + 256 * i];
    }
    if (tid < 128) { s_b1[tid] = b1[tid]; s_b3[tid] = b3[tid]; }

    const int m0 = blockIdx.x * 128;
    {   // stage A (node_feat) -> bf16 hi/lo, uint4 stores
        const int r = tid >> 1;
        const int chunk = tid & 1;
        const int gr = m0 + r;
        const bool valid = gr < N_NODES;
        const float* src = A + (size_t)gr * 128 + chunk * 64;
        #pragma unroll
        for (int j = 0; j < 8; j++) {
            float4 v0 = valid ? *(const float4*)(src + j * 8)
                              : make_float4(0.f, 0.f, 0.f, 0.f);
            float4 v1 = valid ? *(const float4*)(src + j * 8 + 4)
                              : make_float4(0.f, 0.f, 0.f, 0.f);
            uint4 hi, lo;
            split8(v0, v1, hi, lo);
            uint32_t off = swz(r * 128 + j * 16);
            *(uint4*)(smc + PB_A + chunk * 16384 + off) = hi;
            *(uint4*)(smc + PB_A + 32768 + chunk * 16384 + off) = lo;
        }
    }
    __syncthreads();

    const int wr0 = wid * 16;
    const int qr = lid >> 2, qc = (lid & 3) * 2;
    const int r0 = wr0 + qr, r1 = r0 + 8;
    const int am = lid >> 3;
    const int arow = wr0 + ((am & 1) << 3) + (lid & 7);
    const int akof = (am >> 1) << 4;
    const int gr0 = m0 + r0, gr1 = m0 + r1;

    float acc[16][4];
    #pragma unroll
    for (int nt = 0; nt < 16; nt++)
        #pragma unroll
        for (int v = 0; v < 4; v++) acc[nt][v] = 0.f;
    gemm128_core(smb, PB_A, PB_W, lid, arow, akof, acc);
    #pragma unroll
    for (int nt = 0; nt < 16; nt++) {
        const int c = nt * 8 + qc;
        if (gr0 < N_NODES)
            *(float2*)(g_P + (size_t)gr0 * 128 + c) = make_float2(
                acc[nt][0] + s_b1[c], acc[nt][1] + s_b1[c + 1]);
        if (gr1 < N_NODES)
            *(float2*)(g_P + (size_t)gr1 * 128 + c) = make_float2(
                acc[nt][2] + s_b1[c], acc[nt][3] + s_b1[c + 1]);
    }
    __syncthreads();
    {   // swap to W3_top image
        const float4* src = (const float4*)(g_WB + 32768 + 65536);
        float4* dst = (float4*)smc;
        #pragma unroll
        for (int i = 0; i < 16; i++) dst[tid + 256 * i] = src[tid + 256 * i];
    }
    __syncthreads();
    #pragma unroll
    for (int nt = 0; nt < 16; nt++)
        #pragma unroll
        for (int v = 0; v < 4; v++) acc[nt][v] = 0.f;
    gemm128_core(smb, PB_A, PB_W, lid, arow, akof, acc);
    #pragma unroll
    for (int nt = 0; nt < 16; nt++) {
        const int c = nt * 8 + qc;
        if (gr0 < N_NODES)
            *(float2*)(g_P3 + (size_t)gr0 * 128 + c) = make_float2(
                acc[nt][0] + s_b3[c], acc[nt][1] + s_b3[c + 1]);
        if (gr1 < N_NODES)
            *(float2*)(g_P3 + (size_t)gr1 * 128 + c) = make_float2(
                acc[nt][2] + s_b3[c], acc[nt][3] + s_b3[c + 1]);
    }
}

// ---------------------------------------------------------------------------
// node_fused: mean = sums/max(cnt,1); T = relu(P3 + mean@W23 + flag*b23);
// out = T@W4 + b4. T restaged bf16 hi/lo in the A region between GEMMs.
__global__ __launch_bounds__(256, 1)
void node_fused_kernel(const float* __restrict__ b4, float* __restrict__ out) {
    extern __shared__ char smc[];
    const uint32_t smb = smem_u32(smc);
    const int tid = threadIdx.x;
    const int wid = tid >> 5;
    const int lid = tid & 31;
    float* s_b23 = (float*)(smc + PB_BIAS);
    float* s_b4  = s_b23 + 128;

    {   // W23 image
        const float4* src = (const float4*)(g_WB + 32768 + 2 * 65536);
        float4* dst = (float4*)smc;
        #pragma unroll
        for (int i = 0; i < 16; i++) dst[tid + 256 * i] = src[tid + 256 * i];
    }
    if (tid < 128) { s_b23[tid] = g_b23[tid]; s_b4[tid] = b4[tid]; }

    const int m0 = blockIdx.x * 128;
    {   // stage mean -> bf16 hi/lo, uint4 stores
        const int r = tid >> 1;
        const int chunk = tid & 1;
        const int gr = m0 + r;
        const bool valid = gr < N_NODES;
        float s = valid ? 1.f / fmaxf(g_cnt[gr], 1.f) : 0.f;
        const float* src = g_sums + (size_t)gr * 128 + chunk * 64;
        #pragma unroll
        for (int j = 0; j < 8; j++) {
            float4 v0 = valid ? *(const float4*)(src + j * 8)
                              : make_float4(0.f, 0.f, 0.f, 0.f);
            float4 v1 = valid ? *(const float4*)(src + j * 8 + 4)
                              : make_float4(0.f, 0.f, 0.f, 0.f);
            v0.x *= s; v0.y *= s; v0.z *= s; v0.w *= s;
            v1.x *= s; v1.y *= s; v1.z *= s; v1.w *= s;
            uint4 hi, lo;
            split8(v0, v1, hi, lo);
            uint32_t off = swz(r * 128 + j * 16);
            *(uint4*)(smc + PB_A + chunk * 16384 + off) = hi;
            *(uint4*)(smc + PB_A + 32768 + chunk * 16384 + off) = lo;
        }
    }
    __syncthreads();

    const int wr0 = wid * 16;
    const int qr = lid >> 2, qc = (lid & 3) * 2;
    const int r0 = wr0 + qr, r1 = r0 + 8;
    const int am = lid >> 3;
    const int arow = wr0 + ((am & 1) << 3) + (lid & 7);
    const int akof = (am >> 1) << 4;
    const int gr0 = m0 + r0, gr1 = m0 + r1;

    float acc[16][4];
    #pragma unroll
    for (int nt = 0; nt < 16; nt++)
        #pragma unroll
        for (int v = 0; v < 4; v++) acc[nt][v] = 0.f;
    gemm128_core(smb, PB_A, PB_W, lid, arow, akof, acc);

    // T = relu(P3 + acc + flag*b23) -> restage into A region (own warp strip)
    {
        const float f0 = (gr0 < N_NODES && g_cnt[gr0] > 0.f) ? 1.f : 0.f;
        const float f1 = (gr1 < N_NODES && g_cnt[gr1] > 0.f) ? 1.f : 0.f;
        #pragma unroll
        for (int nt = 0; nt < 16; nt++) {
            const int c = nt * 8 + qc;
            float t00 = 0.f, t01 = 0.f, t10 = 0.f, t11 = 0.f;
            if (gr0 < N_NODES) {
                float2 p = *(const float2*)(g_P3 + (size_t)gr0 * 128 + c);
                t00 = fmaxf(p.x + acc[nt][0] + f0 * s_b23[c], 0.f);
                t01 = fmaxf(p.y + acc[nt][1] + f0 * s_b23[c + 1], 0.f);
            }
            if (gr1 < N_NODES) {
                float2 p = *(const float2*)(g_P3 + (size_t)gr1 * 128 + c);
                t10 = fmaxf(p.x + acc[nt][2] + f1 * s_b23[c], 0.f);
                t11 = fmaxf(p.y + acc[nt][3] + f1 * s_b23[c + 1], 0.f);
            }
            uint32_t hi0, lo0, hi1, lo1;
            split2(t00, t01, hi0, lo0);
            split2(t10, t11, hi1, lo1);
            const int chunk = (c >> 6) * 16384;
            const int kk2 = (c & 63) * 2;
            *(uint32_t*)(smc + PB_A + chunk + swz(r0 * 128 + kk2)) = hi0;
            *(uint32_t*)(smc + PB_A + chunk + swz(r1 * 128 + kk2)) = hi1;
            *(uint32_t*)(smc + PB_A + 32768 + chunk + swz(r0 * 128 + kk2)) = lo0;
            *(uint32_t*)(smc + PB_A + 32768 + chunk + swz(r1 * 128 + kk2)) = lo1;
        }
    }
    __syncthreads();
    {   // swap to W4 image
        const float4* src = (const float4*)(g_WB + 32768 + 3 * 65536);
        float4* dst = (float4*)smc;
        #pragma unroll
        for (int i = 0; i < 16; i++) dst[tid + 256 * i] = src[tid + 256 * i];
    }
    __syncthreads();
    #pragma unroll
    for (int nt = 0; nt < 16; nt++)
        #pragma unroll
        for (int v = 0; v < 4; v++) acc[nt][v] = 0.f;
    gemm128_core(smb, PB_A, PB_W, lid, arow, akof, acc);
    #pragma unroll
    for (int nt = 0; nt < 16; nt++) {
        const int c = nt * 8 + qc;
        if (gr0 < N_NODES)
            *(float2*)(out + (size_t)gr0 * 128 + c) = make_float2(
                acc[nt][0] + s_b4[c], acc[nt][1] + s_b4[c + 1]);
        if (gr1 < N_NODES)
            *(float2*)(out + (size_t)gr1 * 128 + c) = make_float2(
                acc[nt][2] + s_b4[c], acc[nt][3] + s_b4[c + 1]);
    }
}

// ---------------------------------------------------------------------------
// Edge kernel: D1 = ea@W1_bot (bf16x3, K=64); scatter relu(D1 + P[col]).
// Double-buffered A staging: ONE __syncthreads per tile; next tile's staging
// (LDG+convert+STS.128) issues between MMA and epilogue so the gather/RED
// epilogue hides the staging latency.
// SMEM: [0,16K) B1hi | 16K B1lo | 32K A0(hi,lo) | 64K A1(hi,lo) | 96K idx x2
#define SM_B1HI 0
#define SM_B1LO 16384
#define SM_A    32768
#define SM_IDX  98304
#define EDGE_SMEM_BYTES (98304 + 2048 + 256)

__global__ __launch_bounds__(256, 2)
void edge_kernel_mma(const float* __restrict__ ea, const int* __restrict__ eidx,
                     int E, int ntiles) {
    extern __shared__ char smc[];
    const uint32_t smb = smem_u32(smc);
    const int tid = threadIdx.x;
    const int wid = tid >> 5;
    const int lid = tid & 31;

    {   // weights once (32 KB)
        const float4* src = (const float4*)g_WB;
        float4* dst = (float4*)smc;
        for (int i = tid; i < 2048; i += 256) dst[i] = src[i];
    }

    // staging lane geometry (2 threads/row)
    const int st_r = tid >> 1;
    const int st_half = tid & 1;

    // MMA lane geometry
    const int wr0 = wid * 16;
    const int qr = lid >> 2;
    const int r0 = wr0 + qr, r1 = r0 + 8;
    const int am = lid >> 3;
    const int arow = wr0 + ((am & 1) << 3) + (lid & 7);
    const int akof = (am >> 1) << 4;
    const int ntoff = lid >> 4;
    const int brow = lid & 7;
    const int bkof = ((lid >> 3) & 1) << 4;
    // epilogue shuffle geometry
    const int cboff = (lid & 2) ? 4 : 0;
    const bool evenlane = ((lid & 1) == 0);
    const int myrow = evenlane ? r0 : r1;

    // ---- stage helper (macro-ish lambda) ----
    auto stage = [&](int tile, int q) {
        const int e0s = tile * 128;
        int* rowq = (int*)(smc + SM_IDX) + q * 256;
        int* colq = rowq + 128;
        if (tid < 128) {
            int e = e0s + tid;
            rowq[tid] = (e < E) ? eidx[e] : 0;
        } else {
            int t = tid - 128, e = e0s + t;
            colq[t] = (e < E) ? eidx[(size_t)E + e] : 0;
        }
        const int e = e0s + st_r;
        const bool valid = e < E;
        const float* src = ea + (size_t)e * EF + st_half * 32;
        const uint32_t abase = (uint32_t)(SM_A + q * 32768);
        #pragma unroll
        for (int j = 0; j < 4; j++) {
            float4 v0 = valid ? *(const float4*)(src + j * 8)
                              : make_float4(0.f, 0.f, 0.f, 0.f);
            float4 v1 = valid ? *(const float4*)(src + j * 8 + 4)
                              : make_float4(0.f, 0.f, 0.f, 0.f);
            uint4 hi, lo;
            split8(v0, v1, hi, lo);
            uint32_t off = swz(st_r * 128 + st_half * 64 + j * 16);
            *(uint4*)(smc + abase + off) = hi;
            *(uint4*)(smc + abase + 16384 + off) = lo;
        }
    };

    // prologue: stage first tile into buffer 0
    if (blockIdx.x < ntiles) stage(blockIdx.x, 0);
    __syncthreads();

    int p = 0;
    for (int tile = blockIdx.x; tile < ntiles; tile += gridDim.x, p ^= 1) {
        const int e0 = tile * 128;
        const int* rowp = (const int*)(smc + SM_IDX) + p * 256;
        const int* colp = rowp + 128;
        const uint32_t aoff = (uint32_t)(SM_A + p * 32768);

        // ---- GEMM1 on buffer p ----
        float acc[16][4];
        #pragma unroll
        for (int nt = 0; nt < 16; nt++)
            #pragma unroll
            for (int v = 0; v < 4; v++) acc[nt][v] = 0.f;
        #pragma unroll
        for (int kt = 0; kt < 4; kt++) {
            const int kb = kt * 32;
            uint32_t ahi[4], alo[4];
            ldsm_x4(ahi, smb + aoff + swz(arow * 128 + kb + akof));
            ldsm_x4(alo, smb + aoff + 16384 + swz(arow * 128 + kb + akof));
            #pragma unroll
            for (int nt = 0; nt < 16; nt += 2) {
                uint32_t bo = swz(((nt + ntoff) * 8 + brow) * 128 + kb + bkof);
                uint32_t bh[4], bl[4];
                ldsm_x4(bh, smb + SM_B1HI + bo);
                ldsm_x4(bl, smb + SM_B1LO + bo);
                mma_bf16(acc[nt],     ahi, bh);
                mma_bf16(acc[nt],     ahi, bl);
                mma_bf16(acc[nt],     alo, bh);
                mma_bf16(acc[nt + 1], ahi, bh + 2);
                mma_bf16(acc[nt + 1], ahi, bl + 2);
                mma_bf16(acc[nt + 1], alo, bh + 2);
            }
        }

        // ---- stage NEXT tile into buffer 1-p (overlaps epilogue) ----
        const int nxt = tile + gridDim.x;
        if (nxt < ntiles) stage(nxt, 1 - p);

        // ---- epilogue: shuffle to float4; h = relu(D1 + P[col]); RED.F32X4
        {
            const bool valid = (e0 + myrow < E);
            const float* Pn = g_P + (size_t)colp[myrow] * 128 + cboff;
            float* Sn = g_sums + (size_t)rowp[myrow] * 128 + cboff;
            #pragma unroll
            for (int nt = 0; nt < 16; nt++) {
                float sA = evenlane ? acc[nt][2] : acc[nt][0];
                float sB = evenlane ? acc[nt][3] : acc[nt][1];
                float rA = __shfl_xor_sync(0xFFFFFFFFu, sA, 1);
                float rB = __shfl_xor_sync(0xFFFFFFFFu, sB, 1);
                float4 v = evenlane
                    ? make_float4(acc[nt][0], acc[nt][1], rA, rB)
                    : make_float4(rA, rB, acc[nt][2], acc[nt][3]);
                if (valid) {
                    float4 pv = *(const float4*)(Pn + nt * 8);
                    v.x = fmaxf(v.x + pv.x, 0.f);
                    v.y = fmaxf(v.y + pv.y, 0.f);
                    v.z = fmaxf(v.z + pv.z, 0.f);
                    v.w = fmaxf(v.w + pv.w, 0.f);
                    atomicAdd((float4*)(Sn + nt * 8), v);
                }
            }
        }
        if (tid < 128 && e0 + tid < E) atomicAdd(&g_cnt[rowp[tid]], 1.0f);

        __syncthreads();   // buffer 1-p fully staged; buffer p free to rewrite
    }
}

// ---------------------------------------------------------------------------
extern "C" void kernel_launch(void* const* d_in, const int* in_sizes, int n_in,
                              void* d_out, int out_size) {
    const float* node_feat = (const float*)d_in[0];
    const int*   eidx      = (const int*)d_in[1];   // int32 (JAX x64 disabled)
    const float* ea        = (const float*)d_in[2];
    const float* W1 = (const float*)d_in[3];
    const float* b1 = (const float*)d_in[4];
    const float* W2 = (const float*)d_in[5];
    const float* b2 = (const float*)d_in[6];
    const float* W3 = (const float*)d_in[7];
    const float* b3 = (const float*)d_in[8];
    const float* W4 = (const float*)d_in[9];
    const float* b4 = (const float*)d_in[10];
    float* out = (float*)d_out;

    const int E = in_sizes[1] / 2;
    const int NBN = (N_NODES + 127) / 128;   // 391
    const int NBE = (E + 127) / 128;         // 12500

    cudaFuncSetAttribute(pre_both_kernel,
                         cudaFuncAttributeMaxDynamicSharedMemorySize, PB_SMEM);
    cudaFuncSetAttribute(node_fused_kernel,
                         cudaFuncAttributeMaxDynamicSharedMemorySize, PB_SMEM);
    cudaFuncSetAttribute(edge_kernel_mma,
                         cudaFuncAttributeMaxDynamicSharedMemorySize, EDGE_SMEM_BYTES);

    zero_kernel<<<1024, 256>>>();
    prep1_kernel<<<129, 128>>>(W2, W3, b2);
    prep2_kernel<<<64, 256>>>(W1, W3, W4);
    pre_both_kernel<<<NBN, 256, PB_SMEM>>>(node_feat, b1, b3);
    edge_kernel_mma<<<296, 256, EDGE_SMEM_BYTES>>>(ea, eidx, E, NBE);
    node_fused_kernel<<<NBN, 256, PB_SMEM>>>(b4, out);
}